// round 13
// baseline (speedup 1.0000x reference)
#include <cuda_runtime.h>
#include <cuda_bf16.h>
#include <cuda_fp16.h>
#include <cstdint>
#include <math.h>

#define B_  4
#define N_  2048
#define C_  1024
#define H_  16
#define D_  64
#define BH_ (B_ * H_)   // 64
#define BN_ (B_ * N_)   // 8192

// ---------------- scratch (device globals; no allocations allowed) ----------
__device__ __half g_xh[(size_t)BN_ * C_];                // x: fp16
__device__ __half g_wqkvh[(size_t)3 * C_ * C_];          // w_qkv: fp16
__device__ __half g_wprojh[(size_t)C_ * C_];             // w_proj: fp16
__device__ __half g_atth[(size_t)BN_ * C_];              // att: fp16
__device__ __half g_qh[(size_t)BH_ * N_ * D_];           // q: fp16, normed+roped+scaled
__device__ __half g_kh[(size_t)BH_ * N_ * D_];           // k: fp16, normed+roped
__device__ __half g_vnh[(size_t)BN_ * C_];               // v: fp16, [b][n][h*64+d]

// =====================================================================
// helpers
// =====================================================================
__device__ __forceinline__ uint32_t smem_u32(const void* p) {
    uint32_t a;
    asm("{ .reg .u64 t; cvta.to.shared.u64 t, %1; cvt.u32.u64 %0, t; }"
        : "=r"(a) : "l"(p));
    return a;
}

__device__ __forceinline__ void cpa16(uint32_t s, const void* g) {
    asm volatile("cp.async.cg.shared.global [%0], [%1], 16;"
                 :: "r"(s), "l"(g) : "memory");
}
#define CP_COMMIT()  asm volatile("cp.async.commit_group;" ::: "memory")
#define CP_WAIT(n)   asm volatile("cp.async.wait_group %0;" :: "n"(n) : "memory")

__device__ __forceinline__ void ldm4(uint32_t addr, uint32_t* r) {
    asm volatile("ldmatrix.sync.aligned.m8n8.x4.shared.b16 {%0,%1,%2,%3}, [%4];"
                 : "=r"(r[0]), "=r"(r[1]), "=r"(r[2]), "=r"(r[3]) : "r"(addr));
}

__device__ __forceinline__ void ldm4t(uint32_t addr, uint32_t* r) {
    asm volatile("ldmatrix.sync.aligned.m8n8.x4.trans.shared.b16 {%0,%1,%2,%3}, [%4];"
                 : "=r"(r[0]), "=r"(r[1]), "=r"(r[2]), "=r"(r[3]) : "r"(addr));
}

__device__ __forceinline__ void mma_f16(float* c, const uint32_t* a, const uint32_t* b) {
    asm volatile(
        "mma.sync.aligned.m16n8k16.row.col.f32.f16.f16.f32 "
        "{%0,%1,%2,%3}, {%4,%5,%6,%7}, {%8,%9}, {%0,%1,%2,%3};"
        : "+f"(c[0]), "+f"(c[1]), "+f"(c[2]), "+f"(c[3])
        : "r"(a[0]), "r"(a[1]), "r"(a[2]), "r"(a[3]), "r"(b[0]), "r"(b[1]));
}

// =====================================================================
// fused fp32 -> fp16 split of x, w_qkv, w_proj (one launch)
// =====================================================================
#define NX_   ((size_t)BN_ * C_)          // 8M
#define NWQ_  ((size_t)3 * C_ * C_)       // 3M
#define NWP_  ((size_t)C_ * C_)           // 1M
__global__ void splitall_kernel(const float* __restrict__ x,
                                const float* __restrict__ wq,
                                const float* __restrict__ wp)
{
    size_t i = ((size_t)blockIdx.x * blockDim.x + threadIdx.x) * 4;
    const float* src;
    __half* dst;
    if (i < NX_)                { src = x + i;               dst = g_xh + i; }
    else if (i < NX_ + NWQ_)    { src = wq + (i - NX_);      dst = g_wqkvh + (i - NX_); }
    else if (i < NX_ + NWQ_ + NWP_) {
        src = wp + (i - NX_ - NWQ_);
        dst = g_wprojh + (i - NX_ - NWQ_);
    } else return;
    float4 v = *(const float4*)src;
    __half2* hp = (__half2*)dst;
    hp[0] = __floats2half2_rn(v.x, v.y);
    hp[1] = __floats2half2_rn(v.z, v.w);
}

// =====================================================================
// fp16 GEMM: CTA 128x256, warp tile 64x64, 4 stages, 1 barrier/iter.
// fuse==1: QKV mode (RMSNorm+RoPE epilogue, fp16 q/k/v outputs).
// fuse==0: plain fp32 store to C (proj).
// =====================================================================
#define STG1 49152
#define GSMEM1 (4 * STG1)
__global__ __launch_bounds__(256, 1)
void gemm1_mma(const __half* __restrict__ A, const __half* __restrict__ Bm,
               float* __restrict__ C, int ldC, int K, int fuse,
               const float* __restrict__ cosd, const float* __restrict__ sind,
               const float* __restrict__ qgam, const float* __restrict__ kgam)
{
    extern __shared__ char smem[];
    const uint32_t sb = smem_u32(smem);
    const int tid  = threadIdx.x;
    const int lane = tid & 31;
    const int wid  = tid >> 5;
    const int m0 = blockIdx.y * 128;
    const int n0 = blockIdx.x * 256;
    const int wm = (wid >> 2) * 64;
    const int wn = (wid & 3) * 64;

    uint32_t sA[4]; const __half* pA[4];
#pragma unroll
    for (int j = 0; j < 4; j++) {
        const int idx = tid + 256 * j;
        const int r = idx >> 3, c = idx & 7;
        sA[j] = (uint32_t)(r * 128 + ((c ^ (r & 7)) << 4));
        pA[j] = A + (size_t)(m0 + r) * K + c * 8;
    }
    uint32_t sB[8]; const __half* pB[8];
#pragma unroll
    for (int j = 0; j < 8; j++) {
        const int idx = tid + 256 * j;
        const int r = idx >> 3, c = idx & 7;
        sB[j] = (uint32_t)(16384 + r * 128 + ((c ^ (r & 7)) << 4));
        pB[j] = Bm + (size_t)(n0 + r) * K + c * 8;
    }

    uint32_t arow[4], brow[4];
#pragma unroll
    for (int mt = 0; mt < 4; mt++)
        arow[mt] = (uint32_t)((wm + mt * 16 + (lane & 15)) * 128);
#pragma unroll
    for (int nt = 0; nt < 4; nt++)
        brow[nt] = (uint32_t)(16384 +
            (wn + nt * 16 + ((lane >> 4) << 3) + (lane & 7)) * 128);
    const int swz = lane & 7;
    const int cA = lane >> 4;
    const int cB = (lane >> 3) & 1;

    float acc[4][8][4];
#pragma unroll
    for (int i = 0; i < 4; i++)
#pragma unroll
        for (int j = 0; j < 8; j++)
#pragma unroll
            for (int r = 0; r < 4; r++) acc[i][j][r] = 0.f;

    const int KT = K >> 6;

    auto load_stage = [&](int buf, int kt) {
        const uint32_t st = sb + buf * STG1;
        const int k0 = kt * 64;
#pragma unroll
        for (int j = 0; j < 4; j++) cpa16(st + sA[j], pA[j] + k0);
#pragma unroll
        for (int j = 0; j < 8; j++) cpa16(st + sB[j], pB[j] + k0);
        CP_COMMIT();
    };

    load_stage(0, 0);
    load_stage(1, 1);
    load_stage(2, 2);

#pragma unroll 1
    for (int kt = 0; kt < KT; kt++) {
        if (kt + 2 < KT)      { CP_WAIT(2); }
        else if (kt + 1 < KT) { CP_WAIT(1); }
        else                  { CP_WAIT(0); }
        __syncthreads();
        if (kt + 3 < KT) load_stage((kt + 3) & 3, kt + 3);

        const uint32_t st = sb + (kt & 3) * STG1;
#pragma unroll
        for (int kk = 0; kk < 4; kk++) {
            uint32_t ah[4][4], bh[4][4];
            const uint32_t swA = (uint32_t)(((kk * 2 + cA) ^ swz) << 4);
            const uint32_t swB = (uint32_t)(((kk * 2 + cB) ^ swz) << 4);
#pragma unroll
            for (int mt = 0; mt < 4; mt++) ldm4(st + arow[mt] + swA, ah[mt]);
#pragma unroll
            for (int nt = 0; nt < 4; nt++) ldm4(st + brow[nt] + swB, bh[nt]);
#pragma unroll
            for (int mt = 0; mt < 4; mt++)
#pragma unroll
                for (int nt = 0; nt < 4; nt++)
#pragma unroll
                    for (int h = 0; h < 2; h++)
                        mma_f16(acc[mt][nt * 2 + h], ah[mt], &bh[nt][h * 2]);
        }
    }

    const int g = lane >> 2, tg = lane & 3;

    if (!fuse) {
#pragma unroll
        for (int mt = 0; mt < 4; mt++)
#pragma unroll
            for (int ng = 0; ng < 8; ng++) {
                const int row = m0 + wm + mt * 16 + g;
                const int col = n0 + wn + ng * 8 + tg * 2;
                *(float2*)&C[(size_t)row * ldC + col] =
                    make_float2(acc[mt][ng][0], acc[mt][ng][1]);
                *(float2*)&C[(size_t)(row + 8) * ldC + col] =
                    make_float2(acc[mt][ng][2], acc[mt][ng][3]);
            }
        return;
    }

    // ---- fused QKV epilogue ----
    const int t = (n0 + wn) >> 6;          // head slot 0..47 (warp-uniform)
    const float QS = 0.125f * 1.4426950408889634f;

#pragma unroll
    for (int mt = 0; mt < 4; mt++) {
#pragma unroll
        for (int half = 0; half < 2; half++) {
            const int row = m0 + wm + mt * 16 + g + half * 8;   // token index
            const int n = row & (N_ - 1);
            const int b = row >> 11;
            if (t >= 32) {
                const int hv = t - 32;
#pragma unroll
                for (int ng = 0; ng < 8; ng++) {
                    const int d = ng * 8 + tg * 2;
                    *(__half2*)&g_vnh[(size_t)row * C_ + hv * D_ + d] =
                        __floats2half2_rn(acc[mt][ng][2 * half],
                                          acc[mt][ng][2 * half + 1]);
                }
            } else {
                float ss = 0.f;
#pragma unroll
                for (int ng = 0; ng < 8; ng++) {
                    const float v0 = acc[mt][ng][2 * half];
                    const float v1 = acc[mt][ng][2 * half + 1];
                    ss += v0 * v0 + v1 * v1;
                }
                ss += __shfl_xor_sync(0xffffffffu, ss, 1);
                ss += __shfl_xor_sync(0xffffffffu, ss, 2);
                const float rn = rsqrtf(ss * (1.f / 64.f) + 1e-6f);
                const int isq = (t < 16);
                const float* gam = isq ? qgam : kgam;
                const int h = t & 15;
                const int bh = b * H_ + h;
                __half* dst = (isq ? g_qh : g_kh) + ((size_t)bh * N_ + n) * D_;
#pragma unroll
                for (int ng = 0; ng < 8; ng++) {
                    const int d = ng * 8 + tg * 2;
                    const float2 gm = *(const float2*)(gam + d);
                    const float2 c = *(const float2*)(cosd + n * D_ + d);
                    const float2 s = *(const float2*)(sind + n * D_ + d);
                    const float a0 = acc[mt][ng][2 * half] * rn * gm.x;
                    const float a1 = acc[mt][ng][2 * half + 1] * rn * gm.y;
                    float o0 = a0 * c.x - a1 * s.x;
                    float o1 = a1 * c.y + a0 * s.y;
                    if (isq) { o0 *= QS; o1 *= QS; }
                    *(__half2*)&dst[d] = __floats2half2_rn(o0, o1);
                }
            }
        }
    }
}

// =====================================================================
// Flash attention fp16: CTA = 256 q-rows, warp = 32 q-rows; K-tile = 64.
// V consumed row-major [s][d] from g_vnh via ldmatrix.trans.
// Softmax: exp2 in fp16x2 (h2exp2) -> P fragments directly; row sums via
// ones-column MMA. smem: Q 32KB + 4 stages of (K 8KB | V 8KB) = 96KB.
// =====================================================================
#define FSTG 16384
#define FLASH_SMEM (32768 + 4 * FSTG)

__global__ __launch_bounds__(256, 1)
void flash_mma(__half* __restrict__ outs)
{
    extern __shared__ char smem[];
    const uint32_t sb = smem_u32(smem);
    const int bh  = blockIdx.y;
    const int q0  = blockIdx.x * 256;
    const int tid = threadIdx.x;
    const int lane = tid & 31;
    const int wid  = tid >> 5;
    const int bb = bh >> 4, hh = bh & 15;

    const __half* qhp = g_qh + (size_t)bh * N_ * D_;
    const __half* khp = g_kh + (size_t)bh * N_ * D_;
    const __half* vhp = g_vnh + (size_t)(bb * N_) * C_ + hh * D_;  // row stride C_

#pragma unroll
    for (int j = 0; j < 8; j++) {
        const int idx = tid + 256 * j;
        const int r = idx >> 3, c = idx & 7;
        const uint32_t so = (uint32_t)(r * 128 + ((c ^ (r & 7)) << 4));
        cpa16(sb + so, qhp + (size_t)(q0 + r) * D_ + c * 8);
    }

    uint32_t soff[4]; const __half* gp[4]; size_t gstride[4];
#pragma unroll
    for (int j = 0; j < 4; j++) {
        const int idx = tid + 256 * j;
        const int plane = idx >> 9;            // 0=K, 1=V
        const int r = (idx >> 3) & 63, c = idx & 7;
        soff[j] = (uint32_t)(plane * 8192 + r * 128 + ((c ^ (r & 7)) << 4));
        if (plane == 0) { gp[j] = khp + (size_t)r * D_ + c * 8; gstride[j] = (size_t)64 * D_; }
        else            { gp[j] = vhp + (size_t)r * C_ + c * 8; gstride[j] = (size_t)64 * C_; }
    }

    auto load_stage = [&](int buf, int kt) {
        const uint32_t st = sb + 32768 + buf * FSTG;
#pragma unroll
        for (int j = 0; j < 4; j++)
            cpa16(st + soff[j], gp[j] + (size_t)kt * gstride[j]);
        CP_COMMIT();
    };

    load_stage(0, 0);
    load_stage(1, 1);
    load_stage(2, 2);

    const int swz = lane & 7;
    const int cA = lane >> 4;
    const int cB = (lane >> 3) & 1;
    uint32_t aoff[2];
#pragma unroll
    for (int mt = 0; mt < 2; mt++)
        aoff[mt] = (uint32_t)((wid * 32 + mt * 16 + (lane & 15)) * 128);
    uint32_t boff[4];
#pragma unroll
    for (int nt = 0; nt < 4; nt++)
        boff[nt] = (uint32_t)((nt * 16 + ((lane >> 4) << 3) + (lane & 7)) * 128);

    const int vs = (lane & 7) + ((lane >> 3) & 1) * 8;   // 0..15
    const int vd = lane >> 4;                            // 0/1

    const uint32_t bone2[2] = {0x3C003C00u, 0x3C003C00u};  // half2(1,1) x2

    float oc[2][8][4];
    float m_r[2][2], l_r[2][2];
#pragma unroll
    for (int mt = 0; mt < 2; mt++) {
#pragma unroll
        for (int i = 0; i < 8; i++)
#pragma unroll
            for (int j = 0; j < 4; j++) oc[mt][i][j] = 0.f;
        m_r[mt][0] = m_r[mt][1] = -1e30f;
        l_r[mt][0] = l_r[mt][1] = 0.f;
    }

    const int KTN = N_ / 64;   // 32
#pragma unroll 1
    for (int kt = 0; kt < KTN; kt++) {
        if (kt + 2 < KTN)      { CP_WAIT(2); }
        else if (kt + 1 < KTN) { CP_WAIT(1); }
        else                   { CP_WAIT(0); }
        __syncthreads();
        if (kt + 3 < KTN) load_stage((kt + 3) & 3, kt + 3);
        const uint32_t st = sb + 32768 + (kt & 3) * FSTG;

        float sc[2][8][4];
#pragma unroll
        for (int mt = 0; mt < 2; mt++)
#pragma unroll
            for (int i = 0; i < 8; i++)
#pragma unroll
                for (int j = 0; j < 4; j++) sc[mt][i][j] = 0.f;

#pragma unroll
        for (int kk = 0; kk < 4; kk++) {
            const uint32_t swA = (uint32_t)(((kk * 2 + cA) ^ swz) << 4);
            const uint32_t swB = (uint32_t)(((kk * 2 + cB) ^ swz) << 4);
            uint32_t aq[2][4];
            ldm4(sb + aoff[0] + swA, aq[0]);
            ldm4(sb + aoff[1] + swA, aq[1]);
#pragma unroll
            for (int nt = 0; nt < 4; nt++) {
                uint32_t kh[4];
                ldm4(st + boff[nt] + swB, kh);
#pragma unroll
                for (int mt = 0; mt < 2; mt++)
#pragma unroll
                    for (int h = 0; h < 2; h++)
                        mma_f16(sc[mt][nt * 2 + h], aq[mt], &kh[h * 2]);
            }
        }

        // ---- online softmax: exp2 in fp16x2; P fragments built directly ----
        float fs[2][2];
        uint32_t hp2[2][8][2];
#pragma unroll
        for (int mt = 0; mt < 2; mt++)
#pragma unroll
            for (int p = 0; p < 2; p++) {
                float mx = -1e30f;
#pragma unroll
                for (int ng = 0; ng < 8; ng++)
                    mx = fmaxf(mx, fmaxf(sc[mt][ng][2 * p], sc[mt][ng][2 * p + 1]));
                mx = fmaxf(mx, __shfl_xor_sync(0xffffffffu, mx, 1));
                mx = fmaxf(mx, __shfl_xor_sync(0xffffffffu, mx, 2));
                const float mnew = fmaxf(m_r[mt][p], mx);
                fs[mt][p] = exp2f(m_r[mt][p] - mnew);
                m_r[mt][p] = mnew;
#pragma unroll
                for (int ng = 0; ng < 8; ng++) {
                    __half2 e = h2exp2(__floats2half2_rn(
                        sc[mt][ng][2 * p] - mnew, sc[mt][ng][2 * p + 1] - mnew));
                    hp2[mt][ng][p] = *(uint32_t*)&e;
                }
#pragma unroll
                for (int dt = 0; dt < 8; dt++) {
                    oc[mt][dt][2 * p] *= fs[mt][p];
                    oc[mt][dt][2 * p + 1] *= fs[mt][p];
                }
            }

        // ---- O += P V ; row sums via ones-MMA ----
        float ts[2][4];
#pragma unroll
        for (int mt = 0; mt < 2; mt++)
#pragma unroll
            for (int r = 0; r < 4; r++) ts[mt][r] = 0.f;

#pragma unroll
        for (int kk = 0; kk < 4; kk++) {
            uint32_t ph[2][4];
#pragma unroll
            for (int mt = 0; mt < 2; mt++) {
#pragma unroll
                for (int u = 0; u < 2; u++)
#pragma unroll
                    for (int v = 0; v < 2; v++)
                        ph[mt][u * 2 + v] = hp2[mt][2 * kk + u][v];
                mma_f16(ts[mt], ph[mt], bone2);   // row sums
            }
            const int s = kk * 16 + vs;
            const uint32_t vrow = (uint32_t)(8192 + s * 128);
            const int sx = s & 7;
#pragma unroll
            for (int nt = 0; nt < 4; nt++) {
                const uint32_t addr = st + vrow +
                    (uint32_t)((((nt * 2 + vd) ^ sx)) << 4);
                uint32_t vh[4];
                ldm4t(addr, vh);
#pragma unroll
                for (int mt = 0; mt < 2; mt++)
#pragma unroll
                    for (int h2 = 0; h2 < 2; h2++)
                        mma_f16(oc[mt][nt * 2 + h2], ph[mt], &vh[h2 * 2]);
            }
        }

#pragma unroll
        for (int mt = 0; mt < 2; mt++) {
            l_r[mt][0] = l_r[mt][0] * fs[mt][0] + ts[mt][0];
            l_r[mt][1] = l_r[mt][1] * fs[mt][1] + ts[mt][2];
        }
    }

    // ---- epilogue ----
#pragma unroll
    for (int mt = 0; mt < 2; mt++)
#pragma unroll
        for (int p = 0; p < 2; p++) {
            const int n = q0 + wid * 32 + mt * 16 + (lane >> 2) + 8 * p;
            const float inv = 1.f / l_r[mt][p];
#pragma unroll
            for (int dt = 0; dt < 8; dt++) {
                const int d = dt * 8 + 2 * (lane & 3);
                const size_t oi = ((size_t)(bb * N_ + n)) * C_ + hh * D_ + d;
                *(__half2*)&outs[oi] = __floats2half2_rn(
                    oc[mt][dt][2 * p] * inv, oc[mt][dt][2 * p + 1] * inv);
            }
        }
}

// =====================================================================
extern "C" void kernel_launch(void* const* d_in, const int* in_sizes, int n_in,
                              void* d_out, int out_size)
{
    const float* x      = (const float*)d_in[0];
    const float* cosd   = (const float*)d_in[1];
    const float* sind   = (const float*)d_in[2];
    const float* w_qkv  = (const float*)d_in[3];
    const float* w_proj = (const float*)d_in[4];
    const float* q_gam  = (const float*)d_in[5];
    const float* k_gam  = (const float*)d_in[6];
    float* out = (float*)d_out;

    __half *p_xh = nullptr, *p_wqkvh = nullptr, *p_atth = nullptr, *p_wprojh = nullptr;
    cudaGetSymbolAddress((void**)&p_xh, g_xh);
    cudaGetSymbolAddress((void**)&p_wqkvh, g_wqkvh);
    cudaGetSymbolAddress((void**)&p_atth, g_atth);
    cudaGetSymbolAddress((void**)&p_wprojh, g_wprojh);

    cudaFuncSetAttribute(gemm1_mma,
                         cudaFuncAttributeMaxDynamicSharedMemorySize, GSMEM1);
    cudaFuncSetAttribute(flash_mma,
                         cudaFuncAttributeMaxDynamicSharedMemorySize, FLASH_SMEM);

    // 1) fused fp32->fp16 split of x, w_qkv, w_proj (one launch)
    const size_t total = NX_ + NWQ_ + NWP_;
    splitall_kernel<<<(int)((total / 4 + 255) / 256), 256>>>(x, w_qkv, w_proj);

    // 2) QKV projection + fused RMSNorm/RoPE/layout epilogue
    gemm1_mma<<<dim3(3 * C_ / 256, BN_ / 128), 256, GSMEM1>>>(
        p_xh, p_wqkvh, nullptr, 3 * C_, C_, 1, cosd, sind, q_gam, k_gam);

    // 3) flash attention
    flash_mma<<<dim3(N_ / 256, BH_), 256, FLASH_SMEM>>>(p_atth);

    // 4) output projection
    gemm1_mma<<<dim3(C_ / 256, BN_ / 128), 256, GSMEM1>>>(
        p_atth, p_wprojh, out, C_, C_, 0, nullptr, nullptr, nullptr, nullptr);
}

// round 14
// speedup vs baseline: 1.0493x; 1.0493x over previous
#include <cuda_runtime.h>
#include <cuda_bf16.h>
#include <cuda_fp16.h>
#include <cstdint>
#include <math.h>

#define B_  4
#define N_  2048
#define C_  1024
#define H_  16
#define D_  64
#define BH_ (B_ * H_)   // 64
#define BN_ (B_ * N_)   // 8192

// ---------------- scratch (device globals; no allocations allowed) ----------
__device__ __half g_xh[(size_t)BN_ * C_];                // x: fp16
__device__ __half g_wqkvh[(size_t)3 * C_ * C_];          // w_qkv: fp16
__device__ __half g_wprojh[(size_t)C_ * C_];             // w_proj: fp16
__device__ __half g_atth[(size_t)BN_ * C_];              // att: fp16
__device__ __half g_qh[(size_t)BH_ * N_ * D_];           // q: fp16, normed+roped+scaled
__device__ __half g_kh[(size_t)BH_ * N_ * D_];           // k: fp16, normed+roped
__device__ __half g_vnh[(size_t)BN_ * C_];               // v: fp16, [b][n][h*64+d]

// =====================================================================
// helpers
// =====================================================================
__device__ __forceinline__ uint32_t smem_u32(const void* p) {
    uint32_t a;
    asm("{ .reg .u64 t; cvta.to.shared.u64 t, %1; cvt.u32.u64 %0, t; }"
        : "=r"(a) : "l"(p));
    return a;
}

__device__ __forceinline__ void cpa16(uint32_t s, const void* g) {
    asm volatile("cp.async.cg.shared.global [%0], [%1], 16;"
                 :: "r"(s), "l"(g) : "memory");
}
#define CP_COMMIT()  asm volatile("cp.async.commit_group;" ::: "memory")
#define CP_WAIT(n)   asm volatile("cp.async.wait_group %0;" :: "n"(n) : "memory")

__device__ __forceinline__ void ldm4(uint32_t addr, uint32_t* r) {
    asm volatile("ldmatrix.sync.aligned.m8n8.x4.shared.b16 {%0,%1,%2,%3}, [%4];"
                 : "=r"(r[0]), "=r"(r[1]), "=r"(r[2]), "=r"(r[3]) : "r"(addr));
}

__device__ __forceinline__ void ldm4t(uint32_t addr, uint32_t* r) {
    asm volatile("ldmatrix.sync.aligned.m8n8.x4.trans.shared.b16 {%0,%1,%2,%3}, [%4];"
                 : "=r"(r[0]), "=r"(r[1]), "=r"(r[2]), "=r"(r[3]) : "r"(addr));
}

__device__ __forceinline__ void mma_f16(float* c, const uint32_t* a, const uint32_t* b) {
    asm volatile(
        "mma.sync.aligned.m16n8k16.row.col.f32.f16.f16.f32 "
        "{%0,%1,%2,%3}, {%4,%5,%6,%7}, {%8,%9}, {%0,%1,%2,%3};"
        : "+f"(c[0]), "+f"(c[1]), "+f"(c[2]), "+f"(c[3])
        : "r"(a[0]), "r"(a[1]), "r"(a[2]), "r"(a[3]), "r"(b[0]), "r"(b[1]));
}

// =====================================================================
// fused fp32 -> fp16 split of x, w_qkv, w_proj (one launch)
// =====================================================================
#define NX_   ((size_t)BN_ * C_)          // 8M
#define NWQ_  ((size_t)3 * C_ * C_)       // 3M
#define NWP_  ((size_t)C_ * C_)           // 1M
__global__ void splitall_kernel(const float* __restrict__ x,
                                const float* __restrict__ wq,
                                const float* __restrict__ wp)
{
    size_t i = ((size_t)blockIdx.x * blockDim.x + threadIdx.x) * 4;
    const float* src;
    __half* dst;
    if (i < NX_)                { src = x + i;               dst = g_xh + i; }
    else if (i < NX_ + NWQ_)    { src = wq + (i - NX_);      dst = g_wqkvh + (i - NX_); }
    else if (i < NX_ + NWQ_ + NWP_) {
        src = wp + (i - NX_ - NWQ_);
        dst = g_wprojh + (i - NX_ - NWQ_);
    } else return;
    float4 v = *(const float4*)src;
    __half2* hp = (__half2*)dst;
    hp[0] = __floats2half2_rn(v.x, v.y);
    hp[1] = __floats2half2_rn(v.z, v.w);
}

// =====================================================================
// fp16 GEMM: CTA 128x256, warp tile 64x64, 4 stages, 1 barrier/iter.
// fuse==1: QKV mode (RMSNorm+RoPE epilogue, fp16 q/k/v outputs).
// fuse==0: plain fp32 store to C (proj).
// =====================================================================
#define STG1 49152
#define GSMEM1 (4 * STG1)
__global__ __launch_bounds__(256, 1)
void gemm1_mma(const __half* __restrict__ A, const __half* __restrict__ Bm,
               float* __restrict__ C, int ldC, int K, int fuse,
               const float* __restrict__ cosd, const float* __restrict__ sind,
               const float* __restrict__ qgam, const float* __restrict__ kgam)
{
    extern __shared__ char smem[];
    const uint32_t sb = smem_u32(smem);
    const int tid  = threadIdx.x;
    const int lane = tid & 31;
    const int wid  = tid >> 5;
    const int m0 = blockIdx.y * 128;
    const int n0 = blockIdx.x * 256;
    const int wm = (wid >> 2) * 64;
    const int wn = (wid & 3) * 64;

    uint32_t sA[4]; const __half* pA[4];
#pragma unroll
    for (int j = 0; j < 4; j++) {
        const int idx = tid + 256 * j;
        const int r = idx >> 3, c = idx & 7;
        sA[j] = (uint32_t)(r * 128 + ((c ^ (r & 7)) << 4));
        pA[j] = A + (size_t)(m0 + r) * K + c * 8;
    }
    uint32_t sB[8]; const __half* pB[8];
#pragma unroll
    for (int j = 0; j < 8; j++) {
        const int idx = tid + 256 * j;
        const int r = idx >> 3, c = idx & 7;
        sB[j] = (uint32_t)(16384 + r * 128 + ((c ^ (r & 7)) << 4));
        pB[j] = Bm + (size_t)(n0 + r) * K + c * 8;
    }

    uint32_t arow[4], brow[4];
#pragma unroll
    for (int mt = 0; mt < 4; mt++)
        arow[mt] = (uint32_t)((wm + mt * 16 + (lane & 15)) * 128);
#pragma unroll
    for (int nt = 0; nt < 4; nt++)
        brow[nt] = (uint32_t)(16384 +
            (wn + nt * 16 + ((lane >> 4) << 3) + (lane & 7)) * 128);
    const int swz = lane & 7;
    const int cA = lane >> 4;
    const int cB = (lane >> 3) & 1;

    float acc[4][8][4];
#pragma unroll
    for (int i = 0; i < 4; i++)
#pragma unroll
        for (int j = 0; j < 8; j++)
#pragma unroll
            for (int r = 0; r < 4; r++) acc[i][j][r] = 0.f;

    const int KT = K >> 6;

    auto load_stage = [&](int buf, int kt) {
        const uint32_t st = sb + buf * STG1;
        const int k0 = kt * 64;
#pragma unroll
        for (int j = 0; j < 4; j++) cpa16(st + sA[j], pA[j] + k0);
#pragma unroll
        for (int j = 0; j < 8; j++) cpa16(st + sB[j], pB[j] + k0);
        CP_COMMIT();
    };

    load_stage(0, 0);
    load_stage(1, 1);
    load_stage(2, 2);

#pragma unroll 1
    for (int kt = 0; kt < KT; kt++) {
        if (kt + 2 < KT)      { CP_WAIT(2); }
        else if (kt + 1 < KT) { CP_WAIT(1); }
        else                  { CP_WAIT(0); }
        __syncthreads();
        if (kt + 3 < KT) load_stage((kt + 3) & 3, kt + 3);

        const uint32_t st = sb + (kt & 3) * STG1;
#pragma unroll
        for (int kk = 0; kk < 4; kk++) {
            uint32_t ah[4][4], bh[4][4];
            const uint32_t swA = (uint32_t)(((kk * 2 + cA) ^ swz) << 4);
            const uint32_t swB = (uint32_t)(((kk * 2 + cB) ^ swz) << 4);
#pragma unroll
            for (int mt = 0; mt < 4; mt++) ldm4(st + arow[mt] + swA, ah[mt]);
#pragma unroll
            for (int nt = 0; nt < 4; nt++) ldm4(st + brow[nt] + swB, bh[nt]);
#pragma unroll
            for (int mt = 0; mt < 4; mt++)
#pragma unroll
                for (int nt = 0; nt < 4; nt++)
#pragma unroll
                    for (int h = 0; h < 2; h++)
                        mma_f16(acc[mt][nt * 2 + h], ah[mt], &bh[nt][h * 2]);
        }
    }

    const int g = lane >> 2, tg = lane & 3;

    if (!fuse) {
#pragma unroll
        for (int mt = 0; mt < 4; mt++)
#pragma unroll
            for (int ng = 0; ng < 8; ng++) {
                const int row = m0 + wm + mt * 16 + g;
                const int col = n0 + wn + ng * 8 + tg * 2;
                *(float2*)&C[(size_t)row * ldC + col] =
                    make_float2(acc[mt][ng][0], acc[mt][ng][1]);
                *(float2*)&C[(size_t)(row + 8) * ldC + col] =
                    make_float2(acc[mt][ng][2], acc[mt][ng][3]);
            }
        return;
    }

    // ---- fused QKV epilogue ----
    const int t = (n0 + wn) >> 6;          // head slot 0..47 (warp-uniform)
    const float QS = 0.125f * 1.4426950408889634f;

#pragma unroll
    for (int mt = 0; mt < 4; mt++) {
#pragma unroll
        for (int half = 0; half < 2; half++) {
            const int row = m0 + wm + mt * 16 + g + half * 8;   // token index
            const int n = row & (N_ - 1);
            const int b = row >> 11;
            if (t >= 32) {
                const int hv = t - 32;
#pragma unroll
                for (int ng = 0; ng < 8; ng++) {
                    const int d = ng * 8 + tg * 2;
                    *(__half2*)&g_vnh[(size_t)row * C_ + hv * D_ + d] =
                        __floats2half2_rn(acc[mt][ng][2 * half],
                                          acc[mt][ng][2 * half + 1]);
                }
            } else {
                float ss = 0.f;
#pragma unroll
                for (int ng = 0; ng < 8; ng++) {
                    const float v0 = acc[mt][ng][2 * half];
                    const float v1 = acc[mt][ng][2 * half + 1];
                    ss += v0 * v0 + v1 * v1;
                }
                ss += __shfl_xor_sync(0xffffffffu, ss, 1);
                ss += __shfl_xor_sync(0xffffffffu, ss, 2);
                const float rn = rsqrtf(ss * (1.f / 64.f) + 1e-6f);
                const int isq = (t < 16);
                const float* gam = isq ? qgam : kgam;
                const int h = t & 15;
                const int bh = b * H_ + h;
                __half* dst = (isq ? g_qh : g_kh) + ((size_t)bh * N_ + n) * D_;
#pragma unroll
                for (int ng = 0; ng < 8; ng++) {
                    const int d = ng * 8 + tg * 2;
                    const float2 gm = *(const float2*)(gam + d);
                    const float2 c = *(const float2*)(cosd + n * D_ + d);
                    const float2 s = *(const float2*)(sind + n * D_ + d);
                    const float a0 = acc[mt][ng][2 * half] * rn * gm.x;
                    const float a1 = acc[mt][ng][2 * half + 1] * rn * gm.y;
                    float o0 = a0 * c.x - a1 * s.x;
                    float o1 = a1 * c.y + a0 * s.y;
                    if (isq) { o0 *= QS; o1 *= QS; }
                    *(__half2*)&dst[d] = __floats2half2_rn(o0, o1);
                }
            }
        }
    }
}

// =====================================================================
// Flash attention fp16 (R12 numerics): CTA = 128 q-rows, warp = 16 rows;
// K-tile = 64. V row-major via ldmatrix.trans.
// smem: Q[128][64] 16KB + 4 stages of (K 8KB | V 8KB) = 80KB -> 2 CTAs/SM.
// =====================================================================
#define FSTG 16384
#define FLASH_SMEM (16384 + 4 * FSTG)

__global__ __launch_bounds__(256, 2)
void flash_mma(__half* __restrict__ outs)
{
    extern __shared__ char smem[];
    const uint32_t sb = smem_u32(smem);
    const int bh  = blockIdx.y;
    const int q0  = blockIdx.x * 128;
    const int tid = threadIdx.x;
    const int lane = tid & 31;
    const int wid  = tid >> 5;
    const int bb = bh >> 4, hh = bh & 15;

    const __half* qhp = g_qh + (size_t)bh * N_ * D_;
    const __half* khp = g_kh + (size_t)bh * N_ * D_;
    const __half* vhp = g_vnh + (size_t)(bb * N_) * C_ + hh * D_;  // row stride C_

    // Q resident (16KB): 1024 chunks, 4/thread
#pragma unroll
    for (int j = 0; j < 4; j++) {
        const int idx = tid + 256 * j;
        const int r = idx >> 3, c = idx & 7;
        const uint32_t so = (uint32_t)(r * 128 + ((c ^ (r & 7)) << 4));
        cpa16(sb + so, qhp + (size_t)(q0 + r) * D_ + c * 8);
    }

    // stage chunks: K 512 + V 512, 4 per thread. Both [s][d] row-major.
    uint32_t soff[4]; const __half* gp[4]; size_t gstride[4];
#pragma unroll
    for (int j = 0; j < 4; j++) {
        const int idx = tid + 256 * j;
        const int plane = idx >> 9;            // 0=K, 1=V
        const int r = (idx >> 3) & 63, c = idx & 7;
        soff[j] = (uint32_t)(plane * 8192 + r * 128 + ((c ^ (r & 7)) << 4));
        if (plane == 0) { gp[j] = khp + (size_t)r * D_ + c * 8; gstride[j] = (size_t)64 * D_; }
        else            { gp[j] = vhp + (size_t)r * C_ + c * 8; gstride[j] = (size_t)64 * C_; }
    }

    auto load_stage = [&](int buf, int kt) {
        const uint32_t st = sb + 16384 + buf * FSTG;
#pragma unroll
        for (int j = 0; j < 4; j++)
            cpa16(st + soff[j], gp[j] + (size_t)kt * gstride[j]);
        CP_COMMIT();
    };

    load_stage(0, 0);
    load_stage(1, 1);
    load_stage(2, 2);

    const int swz = lane & 7;
    const int cA = lane >> 4;
    const int cB = (lane >> 3) & 1;
    const uint32_t aoff = (uint32_t)((wid * 16 + (lane & 15)) * 128);
    uint32_t boff[4];
#pragma unroll
    for (int nt = 0; nt < 4; nt++)
        boff[nt] = (uint32_t)((nt * 16 + ((lane >> 4) << 3) + (lane & 7)) * 128);

    const int vs = (lane & 7) + ((lane >> 3) & 1) * 8;   // 0..15
    const int vd = lane >> 4;                            // 0/1

    float oc[8][4];
    float m_r[2], l_r[2];
#pragma unroll
    for (int i = 0; i < 8; i++)
#pragma unroll
        for (int j = 0; j < 4; j++) oc[i][j] = 0.f;
    m_r[0] = m_r[1] = -1e30f;
    l_r[0] = l_r[1] = 0.f;

    const int KTN = N_ / 64;   // 32
#pragma unroll 1
    for (int kt = 0; kt < KTN; kt++) {
        if (kt + 2 < KTN)      { CP_WAIT(2); }
        else if (kt + 1 < KTN) { CP_WAIT(1); }
        else                   { CP_WAIT(0); }
        __syncthreads();
        if (kt + 3 < KTN) load_stage((kt + 3) & 3, kt + 3);
        const uint32_t st = sb + 16384 + (kt & 3) * FSTG;

        // ---- S = Q K^T (64 keys), log2 units ----
        float sc[8][4];
#pragma unroll
        for (int i = 0; i < 8; i++)
#pragma unroll
            for (int j = 0; j < 4; j++) sc[i][j] = 0.f;

#pragma unroll
        for (int kk = 0; kk < 4; kk++) {
            const uint32_t swA = (uint32_t)(((kk * 2 + cA) ^ swz) << 4);
            const uint32_t swB = (uint32_t)(((kk * 2 + cB) ^ swz) << 4);
            uint32_t aq[4];
            ldm4(sb + aoff + swA, aq);
#pragma unroll
            for (int nt = 0; nt < 4; nt++) {
                uint32_t kh[4];
                ldm4(st + boff[nt] + swB, kh);
#pragma unroll
                for (int h = 0; h < 2; h++)
                    mma_f16(sc[nt * 2 + h], aq, &kh[h * 2]);
            }
        }

        // ---- online softmax (fp32 exp2, R12 numerics) ----
#pragma unroll
        for (int p = 0; p < 2; p++) {
            float mx = -1e30f;
#pragma unroll
            for (int ng = 0; ng < 8; ng++)
                mx = fmaxf(mx, fmaxf(sc[ng][2 * p], sc[ng][2 * p + 1]));
            mx = fmaxf(mx, __shfl_xor_sync(0xffffffffu, mx, 1));
            mx = fmaxf(mx, __shfl_xor_sync(0xffffffffu, mx, 2));
            const float mnew = fmaxf(m_r[p], mx);
            const float f = exp2f(m_r[p] - mnew);
            m_r[p] = mnew;
            float rs = 0.f;
#pragma unroll
            for (int ng = 0; ng < 8; ng++) {
                sc[ng][2 * p]     = exp2f(sc[ng][2 * p] - mnew);
                sc[ng][2 * p + 1] = exp2f(sc[ng][2 * p + 1] - mnew);
                rs += sc[ng][2 * p] + sc[ng][2 * p + 1];
            }
            rs += __shfl_xor_sync(0xffffffffu, rs, 1);
            rs += __shfl_xor_sync(0xffffffffu, rs, 2);
            l_r[p] = l_r[p] * f + rs;
#pragma unroll
            for (int dt = 0; dt < 8; dt++) {
                oc[dt][2 * p] *= f;
                oc[dt][2 * p + 1] *= f;
            }
        }

        // ---- O += P V : V via ldmatrix.trans on [s][d] rows ----
#pragma unroll
        for (int kk = 0; kk < 4; kk++) {
            uint32_t ph[4];
#pragma unroll
            for (int u = 0; u < 2; u++) {
                const int ng = 2 * kk + u;
#pragma unroll
                for (int v = 0; v < 2; v++) {
                    __half2 hq = __floats2half2_rn(sc[ng][2 * v],
                                                   sc[ng][2 * v + 1]);
                    ph[u * 2 + v] = *(uint32_t*)&hq;
                }
            }
            const int s = kk * 16 + vs;                    // V row 0..63
            const uint32_t vrow = (uint32_t)(8192 + s * 128);
            const int sx = s & 7;
#pragma unroll
            for (int nt = 0; nt < 4; nt++) {
                const uint32_t addr = st + vrow +
                    (uint32_t)((((nt * 2 + vd) ^ sx)) << 4);
                uint32_t vh[4];
                ldm4t(addr, vh);
#pragma unroll
                for (int h2 = 0; h2 < 2; h2++)
                    mma_f16(oc[nt * 2 + h2], ph, &vh[h2 * 2]);
            }
        }
    }

    // ---- epilogue ----
#pragma unroll
    for (int p = 0; p < 2; p++) {
        const int n = q0 + wid * 16 + (lane >> 2) + 8 * p;
        const float inv = 1.f / l_r[p];
#pragma unroll
        for (int dt = 0; dt < 8; dt++) {
            const int d = dt * 8 + 2 * (lane & 3);
            const size_t oi = ((size_t)(bb * N_ + n)) * C_ + hh * D_ + d;
            *(__half2*)&outs[oi] = __floats2half2_rn(
                oc[dt][2 * p] * inv, oc[dt][2 * p + 1] * inv);
        }
    }
}

// =====================================================================
extern "C" void kernel_launch(void* const* d_in, const int* in_sizes, int n_in,
                              void* d_out, int out_size)
{
    const float* x      = (const float*)d_in[0];
    const float* cosd   = (const float*)d_in[1];
    const float* sind   = (const float*)d_in[2];
    const float* w_qkv  = (const float*)d_in[3];
    const float* w_proj = (const float*)d_in[4];
    const float* q_gam  = (const float*)d_in[5];
    const float* k_gam  = (const float*)d_in[6];
    float* out = (float*)d_out;

    __half *p_xh = nullptr, *p_wqkvh = nullptr, *p_atth = nullptr, *p_wprojh = nullptr;
    cudaGetSymbolAddress((void**)&p_xh, g_xh);
    cudaGetSymbolAddress((void**)&p_wqkvh, g_wqkvh);
    cudaGetSymbolAddress((void**)&p_atth, g_atth);
    cudaGetSymbolAddress((void**)&p_wprojh, g_wprojh);

    cudaFuncSetAttribute(gemm1_mma,
                         cudaFuncAttributeMaxDynamicSharedMemorySize, GSMEM1);
    cudaFuncSetAttribute(flash_mma,
                         cudaFuncAttributeMaxDynamicSharedMemorySize, FLASH_SMEM);

    // 1) fused fp32->fp16 split of x, w_qkv, w_proj (one launch)
    const size_t total = NX_ + NWQ_ + NWP_;
    splitall_kernel<<<(int)((total / 4 + 255) / 256), 256>>>(x, w_qkv, w_proj);

    // 2) QKV projection + fused RMSNorm/RoPE/layout epilogue
    gemm1_mma<<<dim3(3 * C_ / 256, BN_ / 128), 256, GSMEM1>>>(
        p_xh, p_wqkvh, nullptr, 3 * C_, C_, 1, cosd, sind, q_gam, k_gam);

    // 3) flash attention (128 q-rows/CTA, 2 CTAs/SM)
    flash_mma<<<dim3(N_ / 128, BH_), 256, FLASH_SMEM>>>(p_atth);

    // 4) output projection
    gemm1_mma<<<dim3(C_ / 256, BN_ / 128), 256, GSMEM1>>>(
        p_atth, p_wprojh, out, C_, C_, 0, nullptr, nullptr, nullptr, nullptr);
}

// round 15
// speedup vs baseline: 1.1225x; 1.0698x over previous
#include <cuda_runtime.h>
#include <cuda_bf16.h>
#include <cuda_fp16.h>
#include <cstdint>
#include <math.h>

#define B_  4
#define N_  2048
#define C_  1024
#define H_  16
#define D_  64
#define BH_ (B_ * H_)   // 64
#define BN_ (B_ * N_)   // 8192

// ---------------- scratch (device globals; no allocations allowed) ----------
__device__ __half g_xh[(size_t)BN_ * C_];                // x: fp16
__device__ __half g_wqkvh[(size_t)3 * C_ * C_];          // w_qkv: fp16
__device__ __half g_wprojh[(size_t)C_ * C_];             // w_proj: fp16
__device__ __half g_atth[(size_t)BN_ * C_];              // att: fp16
__device__ __half g_qh[(size_t)BH_ * N_ * D_];           // q: fp16, normed+roped+scaled
__device__ __half g_kh[(size_t)BH_ * N_ * D_];           // k: fp16, normed+roped
__device__ __half g_vnh[(size_t)BN_ * C_];               // v: fp16, [b][n][h*64+d]

// =====================================================================
// helpers
// =====================================================================
__device__ __forceinline__ uint32_t smem_u32(const void* p) {
    uint32_t a;
    asm("{ .reg .u64 t; cvta.to.shared.u64 t, %1; cvt.u32.u64 %0, t; }"
        : "=r"(a) : "l"(p));
    return a;
}

__device__ __forceinline__ void cpa16(uint32_t s, const void* g) {
    asm volatile("cp.async.cg.shared.global [%0], [%1], 16;"
                 :: "r"(s), "l"(g) : "memory");
}
#define CP_COMMIT()  asm volatile("cp.async.commit_group;" ::: "memory")
#define CP_WAIT(n)   asm volatile("cp.async.wait_group %0;" :: "n"(n) : "memory")

__device__ __forceinline__ void ldm4(uint32_t addr, uint32_t* r) {
    asm volatile("ldmatrix.sync.aligned.m8n8.x4.shared.b16 {%0,%1,%2,%3}, [%4];"
                 : "=r"(r[0]), "=r"(r[1]), "=r"(r[2]), "=r"(r[3]) : "r"(addr));
}

__device__ __forceinline__ void ldm4t(uint32_t addr, uint32_t* r) {
    asm volatile("ldmatrix.sync.aligned.m8n8.x4.trans.shared.b16 {%0,%1,%2,%3}, [%4];"
                 : "=r"(r[0]), "=r"(r[1]), "=r"(r[2]), "=r"(r[3]) : "r"(addr));
}

__device__ __forceinline__ void mma_f16(float* c, const uint32_t* a, const uint32_t* b) {
    asm volatile(
        "mma.sync.aligned.m16n8k16.row.col.f32.f16.f16.f32 "
        "{%0,%1,%2,%3}, {%4,%5,%6,%7}, {%8,%9}, {%0,%1,%2,%3};"
        : "+f"(c[0]), "+f"(c[1]), "+f"(c[2]), "+f"(c[3])
        : "r"(a[0]), "r"(a[1]), "r"(a[2]), "r"(a[3]), "r"(b[0]), "r"(b[1]));
}

// =====================================================================
// fused fp32 -> fp16 split of x, w_qkv, w_proj (one launch)
// =====================================================================
#define NX_   ((size_t)BN_ * C_)          // 8M
#define NWQ_  ((size_t)3 * C_ * C_)       // 3M
#define NWP_  ((size_t)C_ * C_)           // 1M
__global__ void splitall_kernel(const float* __restrict__ x,
                                const float* __restrict__ wq,
                                const float* __restrict__ wp)
{
    size_t i = ((size_t)blockIdx.x * blockDim.x + threadIdx.x) * 4;
    const float* src;
    __half* dst;
    if (i < NX_)                { src = x + i;               dst = g_xh + i; }
    else if (i < NX_ + NWQ_)    { src = wq + (i - NX_);      dst = g_wqkvh + (i - NX_); }
    else if (i < NX_ + NWQ_ + NWP_) {
        src = wp + (i - NX_ - NWQ_);
        dst = g_wprojh + (i - NX_ - NWQ_);
    } else return;
    float4 v = *(const float4*)src;
    __half2* hp = (__half2*)dst;
    hp[0] = __floats2half2_rn(v.x, v.y);
    hp[1] = __floats2half2_rn(v.z, v.w);
}

// =====================================================================
// fp16 GEMM: CTA 128x256, warp tile 64x64, 4 stages, 1 barrier/iter.
// fuse==1: QKV mode (RMSNorm+RoPE epilogue, fp16 q/k/v outputs).
// fuse==0: plain fp32 store to C (proj).
// =====================================================================
#define STG1 49152
#define GSMEM1 (4 * STG1)
__global__ __launch_bounds__(256, 1)
void gemm1_mma(const __half* __restrict__ A, const __half* __restrict__ Bm,
               float* __restrict__ C, int ldC, int K, int fuse,
               const float* __restrict__ cosd, const float* __restrict__ sind,
               const float* __restrict__ qgam, const float* __restrict__ kgam)
{
    extern __shared__ char smem[];
    const uint32_t sb = smem_u32(smem);
    const int tid  = threadIdx.x;
    const int lane = tid & 31;
    const int wid  = tid >> 5;
    const int m0 = blockIdx.y * 128;
    const int n0 = blockIdx.x * 256;
    const int wm = (wid >> 2) * 64;
    const int wn = (wid & 3) * 64;

    uint32_t sA[4]; const __half* pA[4];
#pragma unroll
    for (int j = 0; j < 4; j++) {
        const int idx = tid + 256 * j;
        const int r = idx >> 3, c = idx & 7;
        sA[j] = (uint32_t)(r * 128 + ((c ^ (r & 7)) << 4));
        pA[j] = A + (size_t)(m0 + r) * K + c * 8;
    }
    uint32_t sB[8]; const __half* pB[8];
#pragma unroll
    for (int j = 0; j < 8; j++) {
        const int idx = tid + 256 * j;
        const int r = idx >> 3, c = idx & 7;
        sB[j] = (uint32_t)(16384 + r * 128 + ((c ^ (r & 7)) << 4));
        pB[j] = Bm + (size_t)(n0 + r) * K + c * 8;
    }

    uint32_t arow[4], brow[4];
#pragma unroll
    for (int mt = 0; mt < 4; mt++)
        arow[mt] = (uint32_t)((wm + mt * 16 + (lane & 15)) * 128);
#pragma unroll
    for (int nt = 0; nt < 4; nt++)
        brow[nt] = (uint32_t)(16384 +
            (wn + nt * 16 + ((lane >> 4) << 3) + (lane & 7)) * 128);
    const int swz = lane & 7;
    const int cA = lane >> 4;
    const int cB = (lane >> 3) & 1;

    float acc[4][8][4];
#pragma unroll
    for (int i = 0; i < 4; i++)
#pragma unroll
        for (int j = 0; j < 8; j++)
#pragma unroll
            for (int r = 0; r < 4; r++) acc[i][j][r] = 0.f;

    const int KT = K >> 6;

    auto load_stage = [&](int buf, int kt) {
        const uint32_t st = sb + buf * STG1;
        const int k0 = kt * 64;
#pragma unroll
        for (int j = 0; j < 4; j++) cpa16(st + sA[j], pA[j] + k0);
#pragma unroll
        for (int j = 0; j < 8; j++) cpa16(st + sB[j], pB[j] + k0);
        CP_COMMIT();
    };

    load_stage(0, 0);
    load_stage(1, 1);
    load_stage(2, 2);

#pragma unroll 1
    for (int kt = 0; kt < KT; kt++) {
        if (kt + 2 < KT)      { CP_WAIT(2); }
        else if (kt + 1 < KT) { CP_WAIT(1); }
        else                  { CP_WAIT(0); }
        __syncthreads();
        if (kt + 3 < KT) load_stage((kt + 3) & 3, kt + 3);

        const uint32_t st = sb + (kt & 3) * STG1;
#pragma unroll
        for (int kk = 0; kk < 4; kk++) {
            uint32_t ah[4][4], bh[4][4];
            const uint32_t swA = (uint32_t)(((kk * 2 + cA) ^ swz) << 4);
            const uint32_t swB = (uint32_t)(((kk * 2 + cB) ^ swz) << 4);
#pragma unroll
            for (int mt = 0; mt < 4; mt++) ldm4(st + arow[mt] + swA, ah[mt]);
#pragma unroll
            for (int nt = 0; nt < 4; nt++) ldm4(st + brow[nt] + swB, bh[nt]);
#pragma unroll
            for (int mt = 0; mt < 4; mt++)
#pragma unroll
                for (int nt = 0; nt < 4; nt++)
#pragma unroll
                    for (int h = 0; h < 2; h++)
                        mma_f16(acc[mt][nt * 2 + h], ah[mt], &bh[nt][h * 2]);
        }
    }

    const int g = lane >> 2, tg = lane & 3;

    if (!fuse) {
#pragma unroll
        for (int mt = 0; mt < 4; mt++)
#pragma unroll
            for (int ng = 0; ng < 8; ng++) {
                const int row = m0 + wm + mt * 16 + g;
                const int col = n0 + wn + ng * 8 + tg * 2;
                *(float2*)&C[(size_t)row * ldC + col] =
                    make_float2(acc[mt][ng][0], acc[mt][ng][1]);
                *(float2*)&C[(size_t)(row + 8) * ldC + col] =
                    make_float2(acc[mt][ng][2], acc[mt][ng][3]);
            }
        return;
    }

    // ---- fused QKV epilogue ----
    const int t = (n0 + wn) >> 6;          // head slot 0..47 (warp-uniform)
    const float QS = 0.125f * 1.4426950408889634f;

#pragma unroll
    for (int mt = 0; mt < 4; mt++) {
#pragma unroll
        for (int half = 0; half < 2; half++) {
            const int row = m0 + wm + mt * 16 + g + half * 8;   // token index
            const int n = row & (N_ - 1);
            const int b = row >> 11;
            if (t >= 32) {
                const int hv = t - 32;
#pragma unroll
                for (int ng = 0; ng < 8; ng++) {
                    const int d = ng * 8 + tg * 2;
                    *(__half2*)&g_vnh[(size_t)row * C_ + hv * D_ + d] =
                        __floats2half2_rn(acc[mt][ng][2 * half],
                                          acc[mt][ng][2 * half + 1]);
                }
            } else {
                float ss = 0.f;
#pragma unroll
                for (int ng = 0; ng < 8; ng++) {
                    const float v0 = acc[mt][ng][2 * half];
                    const float v1 = acc[mt][ng][2 * half + 1];
                    ss += v0 * v0 + v1 * v1;
                }
                ss += __shfl_xor_sync(0xffffffffu, ss, 1);
                ss += __shfl_xor_sync(0xffffffffu, ss, 2);
                const float rn = rsqrtf(ss * (1.f / 64.f) + 1e-6f);
                const int isq = (t < 16);
                const float* gam = isq ? qgam : kgam;
                const int h = t & 15;
                const int bh = b * H_ + h;
                __half* dst = (isq ? g_qh : g_kh) + ((size_t)bh * N_ + n) * D_;
#pragma unroll
                for (int ng = 0; ng < 8; ng++) {
                    const int d = ng * 8 + tg * 2;
                    const float2 gm = *(const float2*)(gam + d);
                    const float2 c = *(const float2*)(cosd + n * D_ + d);
                    const float2 s = *(const float2*)(sind + n * D_ + d);
                    const float a0 = acc[mt][ng][2 * half] * rn * gm.x;
                    const float a1 = acc[mt][ng][2 * half + 1] * rn * gm.y;
                    float o0 = a0 * c.x - a1 * s.x;
                    float o1 = a1 * c.y + a0 * s.y;
                    if (isq) { o0 *= QS; o1 *= QS; }
                    *(__half2*)&dst[d] = __floats2half2_rn(o0, o1);
                }
            }
        }
    }
}

// =====================================================================
// Flash attention fp16, static-max softmax (no online rescale):
// RMSNorm bounds |S_log2| <= 11.53, so exp2(S) is always fp16-normal and
// row sums fit fp32. CTA = 128 q-rows, warp = 16 rows; K-tile = 64;
// V row-major via ldmatrix.trans.
// smem: Q[128][64] 16KB + 4 stages of (K 8KB | V 8KB) = 80KB -> 2 CTAs/SM.
// =====================================================================
#define FSTG 16384
#define FLASH_SMEM (16384 + 4 * FSTG)

__global__ __launch_bounds__(256, 2)
void flash_mma(__half* __restrict__ outs)
{
    extern __shared__ char smem[];
    const uint32_t sb = smem_u32(smem);
    const int bh  = blockIdx.y;
    const int q0  = blockIdx.x * 128;
    const int tid = threadIdx.x;
    const int lane = tid & 31;
    const int wid  = tid >> 5;
    const int bb = bh >> 4, hh = bh & 15;

    const __half* qhp = g_qh + (size_t)bh * N_ * D_;
    const __half* khp = g_kh + (size_t)bh * N_ * D_;
    const __half* vhp = g_vnh + (size_t)(bb * N_) * C_ + hh * D_;  // row stride C_

    // Q resident (16KB): 1024 chunks, 4/thread
#pragma unroll
    for (int j = 0; j < 4; j++) {
        const int idx = tid + 256 * j;
        const int r = idx >> 3, c = idx & 7;
        const uint32_t so = (uint32_t)(r * 128 + ((c ^ (r & 7)) << 4));
        cpa16(sb + so, qhp + (size_t)(q0 + r) * D_ + c * 8);
    }

    // stage chunks: K 512 + V 512, 4 per thread. Both [s][d] row-major.
    uint32_t soff[4]; const __half* gp[4]; size_t gstride[4];
#pragma unroll
    for (int j = 0; j < 4; j++) {
        const int idx = tid + 256 * j;
        const int plane = idx >> 9;            // 0=K, 1=V
        const int r = (idx >> 3) & 63, c = idx & 7;
        soff[j] = (uint32_t)(plane * 8192 + r * 128 + ((c ^ (r & 7)) << 4));
        if (plane == 0) { gp[j] = khp + (size_t)r * D_ + c * 8; gstride[j] = (size_t)64 * D_; }
        else            { gp[j] = vhp + (size_t)r * C_ + c * 8; gstride[j] = (size_t)64 * C_; }
    }

    auto load_stage = [&](int buf, int kt) {
        const uint32_t st = sb + 16384 + buf * FSTG;
#pragma unroll
        for (int j = 0; j < 4; j++)
            cpa16(st + soff[j], gp[j] + (size_t)kt * gstride[j]);
        CP_COMMIT();
    };

    load_stage(0, 0);
    load_stage(1, 1);
    load_stage(2, 2);

    const int swz = lane & 7;
    const int cA = lane >> 4;
    const int cB = (lane >> 3) & 1;
    const uint32_t aoff = (uint32_t)((wid * 16 + (lane & 15)) * 128);
    uint32_t boff[4];
#pragma unroll
    for (int nt = 0; nt < 4; nt++)
        boff[nt] = (uint32_t)((nt * 16 + ((lane >> 4) << 3) + (lane & 7)) * 128);

    const int vs = (lane & 7) + ((lane >> 3) & 1) * 8;   // 0..15
    const int vd = lane >> 4;                            // 0/1

    float oc[8][4];
    float l_r[2];
#pragma unroll
    for (int i = 0; i < 8; i++)
#pragma unroll
        for (int j = 0; j < 4; j++) oc[i][j] = 0.f;
    l_r[0] = l_r[1] = 0.f;

    const int KTN = N_ / 64;   // 32
#pragma unroll 1
    for (int kt = 0; kt < KTN; kt++) {
        if (kt + 2 < KTN)      { CP_WAIT(2); }
        else if (kt + 1 < KTN) { CP_WAIT(1); }
        else                   { CP_WAIT(0); }
        __syncthreads();
        if (kt + 3 < KTN) load_stage((kt + 3) & 3, kt + 3);
        const uint32_t st = sb + 16384 + (kt & 3) * FSTG;

        // ---- S = Q K^T (64 keys), log2 units ----
        float sc[8][4];
#pragma unroll
        for (int i = 0; i < 8; i++)
#pragma unroll
            for (int j = 0; j < 4; j++) sc[i][j] = 0.f;

#pragma unroll
        for (int kk = 0; kk < 4; kk++) {
            const uint32_t swA = (uint32_t)(((kk * 2 + cA) ^ swz) << 4);
            const uint32_t swB = (uint32_t)(((kk * 2 + cB) ^ swz) << 4);
            uint32_t aq[4];
            ldm4(sb + aoff + swA, aq);
#pragma unroll
            for (int nt = 0; nt < 4; nt++) {
                uint32_t kh[4];
                ldm4(st + boff[nt] + swB, kh);
#pragma unroll
                for (int h = 0; h < 2; h++)
                    mma_f16(sc[nt * 2 + h], aq, &kh[h * 2]);
            }
        }

        // ---- static-max softmax: exp2 directly, no rescale chain ----
#pragma unroll
        for (int i = 0; i < 8; i++)
#pragma unroll
            for (int j = 0; j < 4; j++) sc[i][j] = exp2f(sc[i][j]);

        float rs0 = 0.f, rs1 = 0.f;
#pragma unroll
        for (int ng = 0; ng < 8; ng++) {
            rs0 += sc[ng][0] + sc[ng][1];
            rs1 += sc[ng][2] + sc[ng][3];
        }
        rs0 += __shfl_xor_sync(0xffffffffu, rs0, 1);
        rs0 += __shfl_xor_sync(0xffffffffu, rs0, 2);
        rs1 += __shfl_xor_sync(0xffffffffu, rs1, 1);
        rs1 += __shfl_xor_sync(0xffffffffu, rs1, 2);
        l_r[0] += rs0;
        l_r[1] += rs1;

        // ---- O += P V : V via ldmatrix.trans on [s][d] rows ----
#pragma unroll
        for (int kk = 0; kk < 4; kk++) {
            uint32_t ph[4];
#pragma unroll
            for (int u = 0; u < 2; u++) {
                const int ng = 2 * kk + u;
#pragma unroll
                for (int v = 0; v < 2; v++) {
                    __half2 hq = __floats2half2_rn(sc[ng][2 * v],
                                                   sc[ng][2 * v + 1]);
                    ph[u * 2 + v] = *(uint32_t*)&hq;
                }
            }
            const int s = kk * 16 + vs;                    // V row 0..63
            const uint32_t vrow = (uint32_t)(8192 + s * 128);
            const int sx = s & 7;
#pragma unroll
            for (int nt = 0; nt < 4; nt++) {
                const uint32_t addr = st + vrow +
                    (uint32_t)((((nt * 2 + vd) ^ sx)) << 4);
                uint32_t vh[4];
                ldm4t(addr, vh);
#pragma unroll
                for (int h2 = 0; h2 < 2; h2++)
                    mma_f16(oc[nt * 2 + h2], ph, &vh[h2 * 2]);
            }
        }
    }

    // ---- epilogue ----
#pragma unroll
    for (int p = 0; p < 2; p++) {
        const int n = q0 + wid * 16 + (lane >> 2) + 8 * p;
        const float inv = 1.f / l_r[p];
#pragma unroll
        for (int dt = 0; dt < 8; dt++) {
            const int d = dt * 8 + 2 * (lane & 3);
            const size_t oi = ((size_t)(bb * N_ + n)) * C_ + hh * D_ + d;
            *(__half2*)&outs[oi] = __floats2half2_rn(
                oc[dt][2 * p] * inv, oc[dt][2 * p + 1] * inv);
        }
    }
}

// =====================================================================
extern "C" void kernel_launch(void* const* d_in, const int* in_sizes, int n_in,
                              void* d_out, int out_size)
{
    const float* x      = (const float*)d_in[0];
    const float* cosd   = (const float*)d_in[1];
    const float* sind   = (const float*)d_in[2];
    const float* w_qkv  = (const float*)d_in[3];
    const float* w_proj = (const float*)d_in[4];
    const float* q_gam  = (const float*)d_in[5];
    const float* k_gam  = (const float*)d_in[6];
    float* out = (float*)d_out;

    __half *p_xh = nullptr, *p_wqkvh = nullptr, *p_atth = nullptr, *p_wprojh = nullptr;
    cudaGetSymbolAddress((void**)&p_xh, g_xh);
    cudaGetSymbolAddress((void**)&p_wqkvh, g_wqkvh);
    cudaGetSymbolAddress((void**)&p_atth, g_atth);
    cudaGetSymbolAddress((void**)&p_wprojh, g_wprojh);

    cudaFuncSetAttribute(gemm1_mma,
                         cudaFuncAttributeMaxDynamicSharedMemorySize, GSMEM1);
    cudaFuncSetAttribute(flash_mma,
                         cudaFuncAttributeMaxDynamicSharedMemorySize, FLASH_SMEM);

    // 1) fused fp32->fp16 split of x, w_qkv, w_proj (one launch)
    const size_t total = NX_ + NWQ_ + NWP_;
    splitall_kernel<<<(int)((total / 4 + 255) / 256), 256>>>(x, w_qkv, w_proj);

    // 2) QKV projection + fused RMSNorm/RoPE/layout epilogue
    gemm1_mma<<<dim3(3 * C_ / 256, BN_ / 128), 256, GSMEM1>>>(
        p_xh, p_wqkvh, nullptr, 3 * C_, C_, 1, cosd, sind, q_gam, k_gam);

    // 3) flash attention (static-max softmax, 2 CTAs/SM)
    flash_mma<<<dim3(N_ / 128, BH_), 256, FLASH_SMEM>>>(p_atth);

    // 4) output projection
    gemm1_mma<<<dim3(C_ / 256, BN_ / 128), 256, GSMEM1>>>(
        p_atth, p_wprojh, out, C_, C_, 0, nullptr, nullptr, nullptr, nullptr);
}

// round 16
// speedup vs baseline: 1.1304x; 1.0070x over previous
#include <cuda_runtime.h>
#include <cuda_bf16.h>
#include <cuda_fp16.h>
#include <cstdint>
#include <math.h>

#define B_  4
#define N_  2048
#define C_  1024
#define H_  16
#define D_  64
#define BH_ (B_ * H_)   // 64
#define BN_ (B_ * N_)   // 8192

// ---------------- scratch (device globals; no allocations allowed) ----------
__device__ __half g_xh[(size_t)BN_ * C_];                // x: fp16
__device__ __half g_wqkvh[(size_t)3 * C_ * C_];          // w_qkv: fp16
__device__ __half g_wprojh[(size_t)C_ * C_];             // w_proj: fp16
__device__ __half g_atth[(size_t)BN_ * C_];              // att: fp16
__device__ __half g_qh[(size_t)BH_ * N_ * D_];           // q: fp16, normed+roped+scaled
__device__ __half g_kh[(size_t)BH_ * N_ * D_];           // k: fp16, normed+roped
__device__ __half g_vnh[(size_t)BN_ * C_];               // v: fp16, [b][n][h*64+d]

// =====================================================================
// helpers
// =====================================================================
__device__ __forceinline__ uint32_t smem_u32(const void* p) {
    uint32_t a;
    asm("{ .reg .u64 t; cvta.to.shared.u64 t, %1; cvt.u32.u64 %0, t; }"
        : "=r"(a) : "l"(p));
    return a;
}

__device__ __forceinline__ void cpa16(uint32_t s, const void* g) {
    asm volatile("cp.async.cg.shared.global [%0], [%1], 16;"
                 :: "r"(s), "l"(g) : "memory");
}
#define CP_COMMIT()  asm volatile("cp.async.commit_group;" ::: "memory")
#define CP_WAIT(n)   asm volatile("cp.async.wait_group %0;" :: "n"(n) : "memory")

__device__ __forceinline__ void ldm4(uint32_t addr, uint32_t* r) {
    asm volatile("ldmatrix.sync.aligned.m8n8.x4.shared.b16 {%0,%1,%2,%3}, [%4];"
                 : "=r"(r[0]), "=r"(r[1]), "=r"(r[2]), "=r"(r[3]) : "r"(addr));
}

__device__ __forceinline__ void ldm4t(uint32_t addr, uint32_t* r) {
    asm volatile("ldmatrix.sync.aligned.m8n8.x4.trans.shared.b16 {%0,%1,%2,%3}, [%4];"
                 : "=r"(r[0]), "=r"(r[1]), "=r"(r[2]), "=r"(r[3]) : "r"(addr));
}

__device__ __forceinline__ void mma_f16(float* c, const uint32_t* a, const uint32_t* b) {
    asm volatile(
        "mma.sync.aligned.m16n8k16.row.col.f32.f16.f16.f32 "
        "{%0,%1,%2,%3}, {%4,%5,%6,%7}, {%8,%9}, {%0,%1,%2,%3};"
        : "+f"(c[0]), "+f"(c[1]), "+f"(c[2]), "+f"(c[3])
        : "r"(a[0]), "r"(a[1]), "r"(a[2]), "r"(a[3]), "r"(b[0]), "r"(b[1]));
}

// =====================================================================
// fused fp32 -> fp16 split of x, w_qkv, w_proj (one launch)
// =====================================================================
#define NX_   ((size_t)BN_ * C_)          // 8M
#define NWQ_  ((size_t)3 * C_ * C_)       // 3M
#define NWP_  ((size_t)C_ * C_)           // 1M
__global__ void splitall_kernel(const float* __restrict__ x,
                                const float* __restrict__ wq,
                                const float* __restrict__ wp)
{
    size_t i = ((size_t)blockIdx.x * blockDim.x + threadIdx.x) * 4;
    const float* src;
    __half* dst;
    if (i < NX_)                { src = x + i;               dst = g_xh + i; }
    else if (i < NX_ + NWQ_)    { src = wq + (i - NX_);      dst = g_wqkvh + (i - NX_); }
    else if (i < NX_ + NWQ_ + NWP_) {
        src = wp + (i - NX_ - NWQ_);
        dst = g_wprojh + (i - NX_ - NWQ_);
    } else return;
    float4 v = *(const float4*)src;
    __half2* hp = (__half2*)dst;
    hp[0] = __floats2half2_rn(v.x, v.y);
    hp[1] = __floats2half2_rn(v.z, v.w);
}

// =====================================================================
// fp16 GEMM: CTA 128x256, warp tile 64x64, 4 stages, 1 barrier/iter.
// fuse==1: QKV mode (RMSNorm+RoPE epilogue, fp16 q/k/v outputs).
// fuse==0: plain fp32 store to C (proj).
// =====================================================================
#define STG1 49152
#define GSMEM1 (4 * STG1)
__global__ __launch_bounds__(256, 1)
void gemm1_mma(const __half* __restrict__ A, const __half* __restrict__ Bm,
               float* __restrict__ C, int ldC, int K, int fuse,
               const float* __restrict__ cosd, const float* __restrict__ sind,
               const float* __restrict__ qgam, const float* __restrict__ kgam)
{
    extern __shared__ char smem[];
    const uint32_t sb = smem_u32(smem);
    const int tid  = threadIdx.x;
    const int lane = tid & 31;
    const int wid  = tid >> 5;
    const int m0 = blockIdx.y * 128;
    const int n0 = blockIdx.x * 256;
    const int wm = (wid >> 2) * 64;
    const int wn = (wid & 3) * 64;

    uint32_t sA[4]; const __half* pA[4];
#pragma unroll
    for (int j = 0; j < 4; j++) {
        const int idx = tid + 256 * j;
        const int r = idx >> 3, c = idx & 7;
        sA[j] = (uint32_t)(r * 128 + ((c ^ (r & 7)) << 4));
        pA[j] = A + (size_t)(m0 + r) * K + c * 8;
    }
    uint32_t sB[8]; const __half* pB[8];
#pragma unroll
    for (int j = 0; j < 8; j++) {
        const int idx = tid + 256 * j;
        const int r = idx >> 3, c = idx & 7;
        sB[j] = (uint32_t)(16384 + r * 128 + ((c ^ (r & 7)) << 4));
        pB[j] = Bm + (size_t)(n0 + r) * K + c * 8;
    }

    uint32_t arow[4], brow[4];
#pragma unroll
    for (int mt = 0; mt < 4; mt++)
        arow[mt] = (uint32_t)((wm + mt * 16 + (lane & 15)) * 128);
#pragma unroll
    for (int nt = 0; nt < 4; nt++)
        brow[nt] = (uint32_t)(16384 +
            (wn + nt * 16 + ((lane >> 4) << 3) + (lane & 7)) * 128);
    const int swz = lane & 7;
    const int cA = lane >> 4;
    const int cB = (lane >> 3) & 1;

    float acc[4][8][4];
#pragma unroll
    for (int i = 0; i < 4; i++)
#pragma unroll
        for (int j = 0; j < 8; j++)
#pragma unroll
            for (int r = 0; r < 4; r++) acc[i][j][r] = 0.f;

    const int KT = K >> 6;

    auto load_stage = [&](int buf, int kt) {
        const uint32_t st = sb + buf * STG1;
        const int k0 = kt * 64;
#pragma unroll
        for (int j = 0; j < 4; j++) cpa16(st + sA[j], pA[j] + k0);
#pragma unroll
        for (int j = 0; j < 8; j++) cpa16(st + sB[j], pB[j] + k0);
        CP_COMMIT();
    };

    load_stage(0, 0);
    load_stage(1, 1);
    load_stage(2, 2);

#pragma unroll 1
    for (int kt = 0; kt < KT; kt++) {
        if (kt + 2 < KT)      { CP_WAIT(2); }
        else if (kt + 1 < KT) { CP_WAIT(1); }
        else                  { CP_WAIT(0); }
        __syncthreads();
        if (kt + 3 < KT) load_stage((kt + 3) & 3, kt + 3);

        const uint32_t st = sb + (kt & 3) * STG1;
#pragma unroll
        for (int kk = 0; kk < 4; kk++) {
            uint32_t ah[4][4], bh[4][4];
            const uint32_t swA = (uint32_t)(((kk * 2 + cA) ^ swz) << 4);
            const uint32_t swB = (uint32_t)(((kk * 2 + cB) ^ swz) << 4);
#pragma unroll
            for (int mt = 0; mt < 4; mt++) ldm4(st + arow[mt] + swA, ah[mt]);
#pragma unroll
            for (int nt = 0; nt < 4; nt++) ldm4(st + brow[nt] + swB, bh[nt]);
#pragma unroll
            for (int mt = 0; mt < 4; mt++)
#pragma unroll
                for (int nt = 0; nt < 4; nt++)
#pragma unroll
                    for (int h = 0; h < 2; h++)
                        mma_f16(acc[mt][nt * 2 + h], ah[mt], &bh[nt][h * 2]);
        }
    }

    const int g = lane >> 2, tg = lane & 3;

    if (!fuse) {
#pragma unroll
        for (int mt = 0; mt < 4; mt++)
#pragma unroll
            for (int ng = 0; ng < 8; ng++) {
                const int row = m0 + wm + mt * 16 + g;
                const int col = n0 + wn + ng * 8 + tg * 2;
                *(float2*)&C[(size_t)row * ldC + col] =
                    make_float2(acc[mt][ng][0], acc[mt][ng][1]);
                *(float2*)&C[(size_t)(row + 8) * ldC + col] =
                    make_float2(acc[mt][ng][2], acc[mt][ng][3]);
            }
        return;
    }

    // ---- fused QKV epilogue ----
    const int t = (n0 + wn) >> 6;          // head slot 0..47 (warp-uniform)
    const float QS = 0.125f * 1.4426950408889634f;

#pragma unroll
    for (int mt = 0; mt < 4; mt++) {
#pragma unroll
        for (int half = 0; half < 2; half++) {
            const int row = m0 + wm + mt * 16 + g + half * 8;   // token index
            const int n = row & (N_ - 1);
            const int b = row >> 11;
            if (t >= 32) {
                const int hv = t - 32;
#pragma unroll
                for (int ng = 0; ng < 8; ng++) {
                    const int d = ng * 8 + tg * 2;
                    *(__half2*)&g_vnh[(size_t)row * C_ + hv * D_ + d] =
                        __floats2half2_rn(acc[mt][ng][2 * half],
                                          acc[mt][ng][2 * half + 1]);
                }
            } else {
                float ss = 0.f;
#pragma unroll
                for (int ng = 0; ng < 8; ng++) {
                    const float v0 = acc[mt][ng][2 * half];
                    const float v1 = acc[mt][ng][2 * half + 1];
                    ss += v0 * v0 + v1 * v1;
                }
                ss += __shfl_xor_sync(0xffffffffu, ss, 1);
                ss += __shfl_xor_sync(0xffffffffu, ss, 2);
                const float rn = rsqrtf(ss * (1.f / 64.f) + 1e-6f);
                const int isq = (t < 16);
                const float* gam = isq ? qgam : kgam;
                const int h = t & 15;
                const int bh = b * H_ + h;
                __half* dst = (isq ? g_qh : g_kh) + ((size_t)bh * N_ + n) * D_;
#pragma unroll
                for (int ng = 0; ng < 8; ng++) {
                    const int d = ng * 8 + tg * 2;
                    const float2 gm = *(const float2*)(gam + d);
                    const float2 c = *(const float2*)(cosd + n * D_ + d);
                    const float2 s = *(const float2*)(sind + n * D_ + d);
                    const float a0 = acc[mt][ng][2 * half] * rn * gm.x;
                    const float a1 = acc[mt][ng][2 * half + 1] * rn * gm.y;
                    float o0 = a0 * c.x - a1 * s.x;
                    float o1 = a1 * c.y + a0 * s.y;
                    if (isq) { o0 *= QS; o1 *= QS; }
                    *(__half2*)&dst[d] = __floats2half2_rn(o0, o1);
                }
            }
        }
    }
}

// =====================================================================
// Flash attention fp16, static-max softmax + h2exp2 + ones-MMA row sums.
// CTA = 128 q-rows, warp = 16 rows; K-tile = 64; V row-major via
// ldmatrix.trans. smem: Q 16KB + 4 stages of (K 8KB | V 8KB) = 80KB
// -> 2 CTAs/SM.
// =====================================================================
#define FSTG 16384
#define FLASH_SMEM (16384 + 4 * FSTG)

__global__ __launch_bounds__(256, 2)
void flash_mma(__half* __restrict__ outs)
{
    extern __shared__ char smem[];
    const uint32_t sb = smem_u32(smem);
    const int bh  = blockIdx.y;
    const int q0  = blockIdx.x * 128;
    const int tid = threadIdx.x;
    const int lane = tid & 31;
    const int wid  = tid >> 5;
    const int bb = bh >> 4, hh = bh & 15;

    const __half* qhp = g_qh + (size_t)bh * N_ * D_;
    const __half* khp = g_kh + (size_t)bh * N_ * D_;
    const __half* vhp = g_vnh + (size_t)(bb * N_) * C_ + hh * D_;  // row stride C_

    // Q resident (16KB): 1024 chunks, 4/thread
#pragma unroll
    for (int j = 0; j < 4; j++) {
        const int idx = tid + 256 * j;
        const int r = idx >> 3, c = idx & 7;
        const uint32_t so = (uint32_t)(r * 128 + ((c ^ (r & 7)) << 4));
        cpa16(sb + so, qhp + (size_t)(q0 + r) * D_ + c * 8);
    }

    // stage chunks: K 512 + V 512, 4 per thread. Both [s][d] row-major.
    uint32_t soff[4]; const __half* gp[4]; size_t gstride[4];
#pragma unroll
    for (int j = 0; j < 4; j++) {
        const int idx = tid + 256 * j;
        const int plane = idx >> 9;            // 0=K, 1=V
        const int r = (idx >> 3) & 63, c = idx & 7;
        soff[j] = (uint32_t)(plane * 8192 + r * 128 + ((c ^ (r & 7)) << 4));
        if (plane == 0) { gp[j] = khp + (size_t)r * D_ + c * 8; gstride[j] = (size_t)64 * D_; }
        else            { gp[j] = vhp + (size_t)r * C_ + c * 8; gstride[j] = (size_t)64 * C_; }
    }

    auto load_stage = [&](int buf, int kt) {
        const uint32_t st = sb + 16384 + buf * FSTG;
#pragma unroll
        for (int j = 0; j < 4; j++)
            cpa16(st + soff[j], gp[j] + (size_t)kt * gstride[j]);
        CP_COMMIT();
    };

    load_stage(0, 0);
    load_stage(1, 1);
    load_stage(2, 2);

    const int swz = lane & 7;
    const int cA = lane >> 4;
    const int cB = (lane >> 3) & 1;
    const uint32_t aoff = (uint32_t)((wid * 16 + (lane & 15)) * 128);
    uint32_t boff[4];
#pragma unroll
    for (int nt = 0; nt < 4; nt++)
        boff[nt] = (uint32_t)((nt * 16 + ((lane >> 4) << 3) + (lane & 7)) * 128);

    const int vs = (lane & 7) + ((lane >> 3) & 1) * 8;   // 0..15
    const int vd = lane >> 4;                            // 0/1

    const uint32_t bone2[2] = {0x3C003C00u, 0x3C003C00u};  // half2(1,1) x2

    float oc[8][4];
    float l_r[2];
#pragma unroll
    for (int i = 0; i < 8; i++)
#pragma unroll
        for (int j = 0; j < 4; j++) oc[i][j] = 0.f;
    l_r[0] = l_r[1] = 0.f;

    const int KTN = N_ / 64;   // 32
#pragma unroll 1
    for (int kt = 0; kt < KTN; kt++) {
        if (kt + 2 < KTN)      { CP_WAIT(2); }
        else if (kt + 1 < KTN) { CP_WAIT(1); }
        else                   { CP_WAIT(0); }
        __syncthreads();
        if (kt + 3 < KTN) load_stage((kt + 3) & 3, kt + 3);
        const uint32_t st = sb + 16384 + (kt & 3) * FSTG;

        // ---- S = Q K^T (64 keys), log2 units ----
        float sc[8][4];
#pragma unroll
        for (int i = 0; i < 8; i++)
#pragma unroll
            for (int j = 0; j < 4; j++) sc[i][j] = 0.f;

#pragma unroll
        for (int kk = 0; kk < 4; kk++) {
            const uint32_t swA = (uint32_t)(((kk * 2 + cA) ^ swz) << 4);
            const uint32_t swB = (uint32_t)(((kk * 2 + cB) ^ swz) << 4);
            uint32_t aq[4];
            ldm4(sb + aoff + swA, aq);
#pragma unroll
            for (int nt = 0; nt < 4; nt++) {
                uint32_t kh[4];
                ldm4(st + boff[nt] + swB, kh);
#pragma unroll
                for (int h = 0; h < 2; h++)
                    mma_f16(sc[nt * 2 + h], aq, &kh[h * 2]);
            }
        }

        // ---- static-max softmax: h2exp2 -> P fragments directly ----
        uint32_t hp2[8][2];
#pragma unroll
        for (int ng = 0; ng < 8; ng++)
#pragma unroll
            for (int v = 0; v < 2; v++) {
                __half2 t = __floats2half2_rn(sc[ng][2 * v], sc[ng][2 * v + 1]);
                t = h2exp2(t);
                hp2[ng][v] = *(uint32_t*)&t;
            }

        // ---- O += P V ; row sums via ones-MMA ----
        float ts[4] = {0.f, 0.f, 0.f, 0.f};
#pragma unroll
        for (int kk = 0; kk < 4; kk++) {
            uint32_t ph[4];
#pragma unroll
            for (int u = 0; u < 2; u++)
#pragma unroll
                for (int v = 0; v < 2; v++)
                    ph[u * 2 + v] = hp2[2 * kk + u][v];
            mma_f16(ts, ph, bone2);   // row sums

            const int s = kk * 16 + vs;                    // V row 0..63
            const uint32_t vrow = (uint32_t)(8192 + s * 128);
            const int sx = s & 7;
#pragma unroll
            for (int nt = 0; nt < 4; nt++) {
                const uint32_t addr = st + vrow +
                    (uint32_t)((((nt * 2 + vd) ^ sx)) << 4);
                uint32_t vh[4];
                ldm4t(addr, vh);
#pragma unroll
                for (int h2 = 0; h2 < 2; h2++)
                    mma_f16(oc[nt * 2 + h2], ph, &vh[h2 * 2]);
            }
        }
        l_r[0] += ts[0];
        l_r[1] += ts[2];
    }

    // ---- epilogue ----
#pragma unroll
    for (int p = 0; p < 2; p++) {
        const int n = q0 + wid * 16 + (lane >> 2) + 8 * p;
        const float inv = 1.f / l_r[p];
#pragma unroll
        for (int dt = 0; dt < 8; dt++) {
            const int d = dt * 8 + 2 * (lane & 3);
            const size_t oi = ((size_t)(bb * N_ + n)) * C_ + hh * D_ + d;
            *(__half2*)&outs[oi] = __floats2half2_rn(
                oc[dt][2 * p] * inv, oc[dt][2 * p + 1] * inv);
        }
    }
}

// =====================================================================
extern "C" void kernel_launch(void* const* d_in, const int* in_sizes, int n_in,
                              void* d_out, int out_size)
{
    const float* x      = (const float*)d_in[0];
    const float* cosd   = (const float*)d_in[1];
    const float* sind   = (const float*)d_in[2];
    const float* w_qkv  = (const float*)d_in[3];
    const float* w_proj = (const float*)d_in[4];
    const float* q_gam  = (const float*)d_in[5];
    const float* k_gam  = (const float*)d_in[6];
    float* out = (float*)d_out;

    __half *p_xh = nullptr, *p_wqkvh = nullptr, *p_atth = nullptr, *p_wprojh = nullptr;
    cudaGetSymbolAddress((void**)&p_xh, g_xh);
    cudaGetSymbolAddress((void**)&p_wqkvh, g_wqkvh);
    cudaGetSymbolAddress((void**)&p_atth, g_atth);
    cudaGetSymbolAddress((void**)&p_wprojh, g_wprojh);

    cudaFuncSetAttribute(gemm1_mma,
                         cudaFuncAttributeMaxDynamicSharedMemorySize, GSMEM1);
    cudaFuncSetAttribute(flash_mma,
                         cudaFuncAttributeMaxDynamicSharedMemorySize, FLASH_SMEM);

    // 1) fused fp32->fp16 split of x, w_qkv, w_proj (one launch)
    const size_t total = NX_ + NWQ_ + NWP_;
    splitall_kernel<<<(int)((total / 4 + 255) / 256), 256>>>(x, w_qkv, w_proj);

    // 2) QKV projection + fused RMSNorm/RoPE/layout epilogue
    gemm1_mma<<<dim3(3 * C_ / 256, BN_ / 128), 256, GSMEM1>>>(
        p_xh, p_wqkvh, nullptr, 3 * C_, C_, 1, cosd, sind, q_gam, k_gam);

    // 3) flash attention (static-max + h2exp2, 2 CTAs/SM)
    flash_mma<<<dim3(N_ / 128, BH_), 256, FLASH_SMEM>>>(p_atth);

    // 4) output projection
    gemm1_mma<<<dim3(C_ / 256, BN_ / 128), 256, GSMEM1>>>(
        p_atth, p_wprojh, out, C_, C_, 0, nullptr, nullptr, nullptr, nullptr);
}

// round 17
// speedup vs baseline: 1.1923x; 1.0548x over previous
#include <cuda_runtime.h>
#include <cuda_bf16.h>
#include <cuda_fp16.h>
#include <cstdint>
#include <math.h>

#define B_  4
#define N_  2048
#define C_  1024
#define H_  16
#define D_  64
#define BH_ (B_ * H_)   // 64
#define BN_ (B_ * N_)   // 8192

// ---------------- scratch (device globals; no allocations allowed) ----------
__device__ __half g_xh[(size_t)BN_ * C_];                // x: fp16
__device__ __half g_wqkvh[(size_t)3 * C_ * C_];          // w_qkv: fp16
__device__ __half g_wprojh[(size_t)C_ * C_];             // w_proj: fp16
__device__ __half g_atth[(size_t)BN_ * C_];              // att: fp16
__device__ __half g_qh[(size_t)BH_ * N_ * D_];           // q: fp16, normed+roped+scaled
__device__ __half g_kh[(size_t)BH_ * N_ * D_];           // k: fp16, normed+roped
__device__ __half g_vnh[(size_t)BN_ * C_];               // v: fp16, [b][n][h*64+d]

// =====================================================================
// helpers
// =====================================================================
__device__ __forceinline__ uint32_t smem_u32(const void* p) {
    uint32_t a;
    asm("{ .reg .u64 t; cvta.to.shared.u64 t, %1; cvt.u32.u64 %0, t; }"
        : "=r"(a) : "l"(p));
    return a;
}

__device__ __forceinline__ void cpa16(uint32_t s, const void* g) {
    asm volatile("cp.async.cg.shared.global [%0], [%1], 16;"
                 :: "r"(s), "l"(g) : "memory");
}
#define CP_COMMIT()  asm volatile("cp.async.commit_group;" ::: "memory")
#define CP_WAIT(n)   asm volatile("cp.async.wait_group %0;" :: "n"(n) : "memory")

__device__ __forceinline__ void ldm4(uint32_t addr, uint32_t* r) {
    asm volatile("ldmatrix.sync.aligned.m8n8.x4.shared.b16 {%0,%1,%2,%3}, [%4];"
                 : "=r"(r[0]), "=r"(r[1]), "=r"(r[2]), "=r"(r[3]) : "r"(addr));
}

__device__ __forceinline__ void ldm4t(uint32_t addr, uint32_t* r) {
    asm volatile("ldmatrix.sync.aligned.m8n8.x4.trans.shared.b16 {%0,%1,%2,%3}, [%4];"
                 : "=r"(r[0]), "=r"(r[1]), "=r"(r[2]), "=r"(r[3]) : "r"(addr));
}

__device__ __forceinline__ void mma_f16(float* c, const uint32_t* a, const uint32_t* b) {
    asm volatile(
        "mma.sync.aligned.m16n8k16.row.col.f32.f16.f16.f32 "
        "{%0,%1,%2,%3}, {%4,%5,%6,%7}, {%8,%9}, {%0,%1,%2,%3};"
        : "+f"(c[0]), "+f"(c[1]), "+f"(c[2]), "+f"(c[3])
        : "r"(a[0]), "r"(a[1]), "r"(a[2]), "r"(a[3]), "r"(b[0]), "r"(b[1]));
}

// =====================================================================
// fused fp32 -> fp16 split of x, w_qkv, w_proj (one launch)
// =====================================================================
#define NX_   ((size_t)BN_ * C_)          // 8M
#define NWQ_  ((size_t)3 * C_ * C_)       // 3M
#define NWP_  ((size_t)C_ * C_)           // 1M
__global__ void splitall_kernel(const float* __restrict__ x,
                                const float* __restrict__ wq,
                                const float* __restrict__ wp)
{
    size_t i = ((size_t)blockIdx.x * blockDim.x + threadIdx.x) * 4;
    const float* src;
    __half* dst;
    if (i < NX_)                { src = x + i;               dst = g_xh + i; }
    else if (i < NX_ + NWQ_)    { src = wq + (i - NX_);      dst = g_wqkvh + (i - NX_); }
    else if (i < NX_ + NWQ_ + NWP_) {
        src = wp + (i - NX_ - NWQ_);
        dst = g_wprojh + (i - NX_ - NWQ_);
    } else return;
    float4 v = *(const float4*)src;
    __half2* hp = (__half2*)dst;
    hp[0] = __floats2half2_rn(v.x, v.y);
    hp[1] = __floats2half2_rn(v.z, v.w);
}

// =====================================================================
// fp16 GEMM: CTA 128x128, 8 warps (4m x 2n), warp tile 32x64.
// 3 stages x 32KB = 96KB -> 2 CTAs/SM. 1 barrier/iter.
// fuse==1: QKV mode (RMSNorm+RoPE epilogue, fp16 q/k/v outputs).
// fuse==0: plain fp32 store to C (proj).
// =====================================================================
#define STG1 32768
#define GSMEM1 (3 * STG1)
__global__ __launch_bounds__(256, 2)
void gemm1_mma(const __half* __restrict__ A, const __half* __restrict__ Bm,
               float* __restrict__ C, int ldC, int K, int fuse,
               const float* __restrict__ cosd, const float* __restrict__ sind,
               const float* __restrict__ qgam, const float* __restrict__ kgam)
{
    extern __shared__ char smem[];
    const uint32_t sb = smem_u32(smem);
    const int tid  = threadIdx.x;
    const int lane = tid & 31;
    const int wid  = tid >> 5;
    const int m0 = blockIdx.y * 128;
    const int n0 = blockIdx.x * 128;
    const int wm = (wid >> 1) * 32;        // 4 m-groups of 32 rows
    const int wn = (wid & 1) * 64;         // 2 n-groups of 64 cols

    // load descriptors: A 1024 chunks (4/thread), B 1024 chunks (4/thread)
    uint32_t sA[4]; const __half* pA[4]; const __half* pB[4];
#pragma unroll
    for (int j = 0; j < 4; j++) {
        const int idx = tid + 256 * j;
        const int r = idx >> 3, c = idx & 7;
        sA[j] = (uint32_t)(r * 128 + ((c ^ (r & 7)) << 4));
        pA[j] = A + (size_t)(m0 + r) * K + c * 8;
        pB[j] = Bm + (size_t)(n0 + r) * K + c * 8;
    }

    uint32_t arow[2], brow[4];
#pragma unroll
    for (int mt = 0; mt < 2; mt++)
        arow[mt] = (uint32_t)((wm + mt * 16 + (lane & 15)) * 128);
#pragma unroll
    for (int nt = 0; nt < 4; nt++)
        brow[nt] = (uint32_t)(16384 +
            (wn + nt * 16 + ((lane >> 4) << 3) + (lane & 7)) * 128);
    const int swz = lane & 7;
    const int cA = lane >> 4;
    const int cB = (lane >> 3) & 1;

    float acc[2][8][4];
#pragma unroll
    for (int i = 0; i < 2; i++)
#pragma unroll
        for (int j = 0; j < 8; j++)
#pragma unroll
            for (int r = 0; r < 4; r++) acc[i][j][r] = 0.f;

    const int KT = K >> 6;

    auto load_stage = [&](int buf, int kt) {
        const uint32_t st = sb + buf * STG1;
        const int k0 = kt * 64;
#pragma unroll
        for (int j = 0; j < 4; j++) {
            cpa16(st + sA[j], pA[j] + k0);
            cpa16(st + 16384 + sA[j], pB[j] + k0);
        }
        CP_COMMIT();
    };

    load_stage(0, 0);
    load_stage(1, 1);

#pragma unroll 1
    for (int kt = 0; kt < KT; kt++) {
        if (kt + 1 < KT) { CP_WAIT(1); } else { CP_WAIT(0); }
        __syncthreads();
        if (kt + 2 < KT) load_stage((kt + 2) % 3, kt + 2);   // buf (kt-1)%3: drained

        const uint32_t st = sb + (kt % 3) * STG1;
#pragma unroll
        for (int kk = 0; kk < 4; kk++) {
            uint32_t ah[2][4], bh[4][4];
            const uint32_t swA = (uint32_t)(((kk * 2 + cA) ^ swz) << 4);
            const uint32_t swB = (uint32_t)(((kk * 2 + cB) ^ swz) << 4);
#pragma unroll
            for (int mt = 0; mt < 2; mt++) ldm4(st + arow[mt] + swA, ah[mt]);
#pragma unroll
            for (int nt = 0; nt < 4; nt++) ldm4(st + brow[nt] + swB, bh[nt]);
#pragma unroll
            for (int mt = 0; mt < 2; mt++)
#pragma unroll
                for (int nt = 0; nt < 4; nt++)
#pragma unroll
                    for (int h = 0; h < 2; h++)
                        mma_f16(acc[mt][nt * 2 + h], ah[mt], &bh[nt][h * 2]);
        }
    }

    const int g = lane >> 2, tg = lane & 3;

    if (!fuse) {
#pragma unroll
        for (int mt = 0; mt < 2; mt++)
#pragma unroll
            for (int ng = 0; ng < 8; ng++) {
                const int row = m0 + wm + mt * 16 + g;
                const int col = n0 + wn + ng * 8 + tg * 2;
                *(float2*)&C[(size_t)row * ldC + col] =
                    make_float2(acc[mt][ng][0], acc[mt][ng][1]);
                *(float2*)&C[(size_t)(row + 8) * ldC + col] =
                    make_float2(acc[mt][ng][2], acc[mt][ng][3]);
            }
        return;
    }

    // ---- fused QKV epilogue (warp n-tile = one 64-wide head slot) ----
    const int t = (n0 + wn) >> 6;          // head slot 0..47 (warp-uniform)
    const float QS = 0.125f * 1.4426950408889634f;

#pragma unroll
    for (int mt = 0; mt < 2; mt++) {
#pragma unroll
        for (int half = 0; half < 2; half++) {
            const int row = m0 + wm + mt * 16 + g + half * 8;   // token index
            const int n = row & (N_ - 1);
            const int b = row >> 11;
            if (t >= 32) {
                const int hv = t - 32;
#pragma unroll
                for (int ng = 0; ng < 8; ng++) {
                    const int d = ng * 8 + tg * 2;
                    *(__half2*)&g_vnh[(size_t)row * C_ + hv * D_ + d] =
                        __floats2half2_rn(acc[mt][ng][2 * half],
                                          acc[mt][ng][2 * half + 1]);
                }
            } else {
                float ss = 0.f;
#pragma unroll
                for (int ng = 0; ng < 8; ng++) {
                    const float v0 = acc[mt][ng][2 * half];
                    const float v1 = acc[mt][ng][2 * half + 1];
                    ss += v0 * v0 + v1 * v1;
                }
                ss += __shfl_xor_sync(0xffffffffu, ss, 1);
                ss += __shfl_xor_sync(0xffffffffu, ss, 2);
                const float rn = rsqrtf(ss * (1.f / 64.f) + 1e-6f);
                const int isq = (t < 16);
                const float* gam = isq ? qgam : kgam;
                const int h = t & 15;
                const int bh = b * H_ + h;
                __half* dst = (isq ? g_qh : g_kh) + ((size_t)bh * N_ + n) * D_;
#pragma unroll
                for (int ng = 0; ng < 8; ng++) {
                    const int d = ng * 8 + tg * 2;
                    const float2 gm = *(const float2*)(gam + d);
                    const float2 c = *(const float2*)(cosd + n * D_ + d);
                    const float2 s = *(const float2*)(sind + n * D_ + d);
                    const float a0 = acc[mt][ng][2 * half] * rn * gm.x;
                    const float a1 = acc[mt][ng][2 * half + 1] * rn * gm.y;
                    float o0 = a0 * c.x - a1 * s.x;
                    float o1 = a1 * c.y + a0 * s.y;
                    if (isq) { o0 *= QS; o1 *= QS; }
                    *(__half2*)&dst[d] = __floats2half2_rn(o0, o1);
                }
            }
        }
    }
}

// =====================================================================
// Flash attention fp16, static-max softmax + h2exp2 + ones-MMA row sums.
// CTA = 128 q-rows, warp = 16 rows; K-tile = 64; V row-major via
// ldmatrix.trans. smem: Q 16KB + 4 stages of (K 8KB | V 8KB) = 80KB
// -> 2 CTAs/SM. (unchanged from R16)
// =====================================================================
#define FSTG 16384
#define FLASH_SMEM (16384 + 4 * FSTG)

__global__ __launch_bounds__(256, 2)
void flash_mma(__half* __restrict__ outs)
{
    extern __shared__ char smem[];
    const uint32_t sb = smem_u32(smem);
    const int bh  = blockIdx.y;
    const int q0  = blockIdx.x * 128;
    const int tid = threadIdx.x;
    const int lane = tid & 31;
    const int wid  = tid >> 5;
    const int bb = bh >> 4, hh = bh & 15;

    const __half* qhp = g_qh + (size_t)bh * N_ * D_;
    const __half* khp = g_kh + (size_t)bh * N_ * D_;
    const __half* vhp = g_vnh + (size_t)(bb * N_) * C_ + hh * D_;  // row stride C_

#pragma unroll
    for (int j = 0; j < 4; j++) {
        const int idx = tid + 256 * j;
        const int r = idx >> 3, c = idx & 7;
        const uint32_t so = (uint32_t)(r * 128 + ((c ^ (r & 7)) << 4));
        cpa16(sb + so, qhp + (size_t)(q0 + r) * D_ + c * 8);
    }

    uint32_t soff[4]; const __half* gp[4]; size_t gstride[4];
#pragma unroll
    for (int j = 0; j < 4; j++) {
        const int idx = tid + 256 * j;
        const int plane = idx >> 9;            // 0=K, 1=V
        const int r = (idx >> 3) & 63, c = idx & 7;
        soff[j] = (uint32_t)(plane * 8192 + r * 128 + ((c ^ (r & 7)) << 4));
        if (plane == 0) { gp[j] = khp + (size_t)r * D_ + c * 8; gstride[j] = (size_t)64 * D_; }
        else            { gp[j] = vhp + (size_t)r * C_ + c * 8; gstride[j] = (size_t)64 * C_; }
    }

    auto load_stage = [&](int buf, int kt) {
        const uint32_t st = sb + 16384 + buf * FSTG;
#pragma unroll
        for (int j = 0; j < 4; j++)
            cpa16(st + soff[j], gp[j] + (size_t)kt * gstride[j]);
        CP_COMMIT();
    };

    load_stage(0, 0);
    load_stage(1, 1);
    load_stage(2, 2);

    const int swz = lane & 7;
    const int cA = lane >> 4;
    const int cB = (lane >> 3) & 1;
    const uint32_t aoff = (uint32_t)((wid * 16 + (lane & 15)) * 128);
    uint32_t boff[4];
#pragma unroll
    for (int nt = 0; nt < 4; nt++)
        boff[nt] = (uint32_t)((nt * 16 + ((lane >> 4) << 3) + (lane & 7)) * 128);

    const int vs = (lane & 7) + ((lane >> 3) & 1) * 8;   // 0..15
    const int vd = lane >> 4;                            // 0/1

    const uint32_t bone2[2] = {0x3C003C00u, 0x3C003C00u};  // half2(1,1) x2

    float oc[8][4];
    float l_r[2];
#pragma unroll
    for (int i = 0; i < 8; i++)
#pragma unroll
        for (int j = 0; j < 4; j++) oc[i][j] = 0.f;
    l_r[0] = l_r[1] = 0.f;

    const int KTN = N_ / 64;   // 32
#pragma unroll 1
    for (int kt = 0; kt < KTN; kt++) {
        if (kt + 2 < KTN)      { CP_WAIT(2); }
        else if (kt + 1 < KTN) { CP_WAIT(1); }
        else                   { CP_WAIT(0); }
        __syncthreads();
        if (kt + 3 < KTN) load_stage((kt + 3) & 3, kt + 3);
        const uint32_t st = sb + 16384 + (kt & 3) * FSTG;

        float sc[8][4];
#pragma unroll
        for (int i = 0; i < 8; i++)
#pragma unroll
            for (int j = 0; j < 4; j++) sc[i][j] = 0.f;

#pragma unroll
        for (int kk = 0; kk < 4; kk++) {
            const uint32_t swA = (uint32_t)(((kk * 2 + cA) ^ swz) << 4);
            const uint32_t swB = (uint32_t)(((kk * 2 + cB) ^ swz) << 4);
            uint32_t aq[4];
            ldm4(sb + aoff + swA, aq);
#pragma unroll
            for (int nt = 0; nt < 4; nt++) {
                uint32_t kh[4];
                ldm4(st + boff[nt] + swB, kh);
#pragma unroll
                for (int h = 0; h < 2; h++)
                    mma_f16(sc[nt * 2 + h], aq, &kh[h * 2]);
            }
        }

        // ---- static-max softmax: h2exp2 -> P fragments directly ----
        uint32_t hp2[8][2];
#pragma unroll
        for (int ng = 0; ng < 8; ng++)
#pragma unroll
            for (int v = 0; v < 2; v++) {
                __half2 t = __floats2half2_rn(sc[ng][2 * v], sc[ng][2 * v + 1]);
                t = h2exp2(t);
                hp2[ng][v] = *(uint32_t*)&t;
            }

        // ---- O += P V ; row sums via ones-MMA ----
        float ts[4] = {0.f, 0.f, 0.f, 0.f};
#pragma unroll
        for (int kk = 0; kk < 4; kk++) {
            uint32_t ph[4];
#pragma unroll
            for (int u = 0; u < 2; u++)
#pragma unroll
                for (int v = 0; v < 2; v++)
                    ph[u * 2 + v] = hp2[2 * kk + u][v];
            mma_f16(ts, ph, bone2);   // row sums

            const int s = kk * 16 + vs;                    // V row 0..63
            const uint32_t vrow = (uint32_t)(8192 + s * 128);
            const int sx = s & 7;
#pragma unroll
            for (int nt = 0; nt < 4; nt++) {
                const uint32_t addr = st + vrow +
                    (uint32_t)((((nt * 2 + vd) ^ sx)) << 4);
                uint32_t vh[4];
                ldm4t(addr, vh);
#pragma unroll
                for (int h2 = 0; h2 < 2; h2++)
                    mma_f16(oc[nt * 2 + h2], ph, &vh[h2 * 2]);
            }
        }
        l_r[0] += ts[0];
        l_r[1] += ts[2];
    }

    // ---- epilogue ----
#pragma unroll
    for (int p = 0; p < 2; p++) {
        const int n = q0 + wid * 16 + (lane >> 2) + 8 * p;
        const float inv = 1.f / l_r[p];
#pragma unroll
        for (int dt = 0; dt < 8; dt++) {
            const int d = dt * 8 + 2 * (lane & 3);
            const size_t oi = ((size_t)(bb * N_ + n)) * C_ + hh * D_ + d;
            *(__half2*)&outs[oi] = __floats2half2_rn(
                oc[dt][2 * p] * inv, oc[dt][2 * p + 1] * inv);
        }
    }
}

// =====================================================================
extern "C" void kernel_launch(void* const* d_in, const int* in_sizes, int n_in,
                              void* d_out, int out_size)
{
    const float* x      = (const float*)d_in[0];
    const float* cosd   = (const float*)d_in[1];
    const float* sind   = (const float*)d_in[2];
    const float* w_qkv  = (const float*)d_in[3];
    const float* w_proj = (const float*)d_in[4];
    const float* q_gam  = (const float*)d_in[5];
    const float* k_gam  = (const float*)d_in[6];
    float* out = (float*)d_out;

    __half *p_xh = nullptr, *p_wqkvh = nullptr, *p_atth = nullptr, *p_wprojh = nullptr;
    cudaGetSymbolAddress((void**)&p_xh, g_xh);
    cudaGetSymbolAddress((void**)&p_wqkvh, g_wqkvh);
    cudaGetSymbolAddress((void**)&p_atth, g_atth);
    cudaGetSymbolAddress((void**)&p_wprojh, g_wprojh);

    cudaFuncSetAttribute(gemm1_mma,
                         cudaFuncAttributeMaxDynamicSharedMemorySize, GSMEM1);
    cudaFuncSetAttribute(flash_mma,
                         cudaFuncAttributeMaxDynamicSharedMemorySize, FLASH_SMEM);

    // 1) fused fp32->fp16 split of x, w_qkv, w_proj (one launch)
    const size_t total = NX_ + NWQ_ + NWP_;
    splitall_kernel<<<(int)((total / 4 + 255) / 256), 256>>>(x, w_qkv, w_proj);

    // 2) QKV projection + fused RMSNorm/RoPE/layout epilogue (occ-2 gemm)
    gemm1_mma<<<dim3(3 * C_ / 128, BN_ / 128), 256, GSMEM1>>>(
        p_xh, p_wqkvh, nullptr, 3 * C_, C_, 1, cosd, sind, q_gam, k_gam);

    // 3) flash attention (static-max + h2exp2, 2 CTAs/SM)
    flash_mma<<<dim3(N_ / 128, BH_), 256, FLASH_SMEM>>>(p_atth);

    // 4) output projection (occ-2 gemm)
    gemm1_mma<<<dim3(C_ / 128, BN_ / 128), 256, GSMEM1>>>(
        p_atth, p_wprojh, out, C_, C_, 0, nullptr, nullptr, nullptr, nullptr);
}